// round 7
// baseline (speedup 1.0000x reference)
#include <cuda_runtime.h>
#include <cuda_bf16.h>
#include <cstdint>

#define NN 50000
#define NE 600000
#define HD 128

#define EDGE_SMEM 108544   // (16896 + 10240) u32 * 4
#define NODE_SMEM 108544
#define P_SMEM    75776    // (8704 + 10240) u32 * 4

// packed-weight plane offsets in g_Wb (uint32 units)
#define EW1_OFF 0          // per layer 2*192*256 = 98304
#define EW2_OFF 983040     // per layer 2*128*128 = 32768
#define NW1_OFF 1310720    // per layer 2*128*256 = 65536
#define NW2_OFF 1966080    // per layer 32768
#define WB_TOTAL 2293760

// ---------------- device scratch ----------------
__device__ float g_h[NN * HD];
__device__ float g_ea[(size_t)NE * HD];
__device__ float g_P1[(size_t)NN * 256];
__device__ float g_P2[(size_t)NN * 256];
__device__ float g_agg[NN * HD];
__device__ float g_inv[NN];
__device__ int   g_cnt[NN];
__device__ int   g_row[NE];
__device__ int   g_col[NE];
__device__ int   g_is64;
__device__ uint32_t g_Wb[WB_TOTAL];

// ---------------- helpers ----------------
__device__ __forceinline__ float gelu(float x) { return x * normcdff(x); }

__device__ __forceinline__ uint32_t pack2(float a, float b) {
    uint32_t r;
    asm("cvt.rn.bf16x2.f32 %0, %1, %2;" : "=r"(r) : "f"(b), "f"(a));
    return r;
}

__device__ __forceinline__ void split2(float a, float b, uint32_t& hi, uint32_t& lo) {
    hi = pack2(a, b);
    float ra = a - __uint_as_float(hi << 16);
    float rb = b - __uint_as_float(hi & 0xffff0000u);
    lo = pack2(ra, rb);
}

__device__ __forceinline__ void mma_bf(float4& d, const uint32_t* a,
                                       uint32_t b0, uint32_t b1) {
    asm("mma.sync.aligned.m16n8k16.row.col.f32.bf16.bf16.f32 "
        "{%0,%1,%2,%3},{%4,%5,%6,%7},{%8,%9},{%0,%1,%2,%3};"
        : "+f"(d.x), "+f"(d.y), "+f"(d.z), "+f"(d.w)
        : "r"(a[0]), "r"(a[1]), "r"(a[2]), "r"(a[3]), "r"(b0), "r"(b1));
}

__device__ __forceinline__ void ldsm_x4(uint32_t* r, uint32_t addr) {
    asm volatile("ldmatrix.sync.aligned.m8n8.x4.shared.b16 {%0,%1,%2,%3}, [%4];"
        : "=r"(r[0]), "=r"(r[1]), "=r"(r[2]), "=r"(r[3]) : "r"(addr));
}

// Stage one weight chunk: global chunk-major [n][16] (N*16 u32 contiguous)
// into smem [n][kp] rows, ld 20 u32 (16B-aligned rows, conflict-free ldmatrix).
__device__ __forceinline__ void stageW(uint32_t* sW, const uint32_t* __restrict__ src,
                                       int N, int tid) {
    for (int t = tid; t < N * 4; t += 256) {
        int n = t >> 2, q = t & 3;
        *(uint4*)&sW[n * 20 + q * 4] = *(const uint4*)&src[n * 16 + q * 4];
    }
}

// One k32 chunk (two m16n8k16 steps), 3-term bf16-split MMA, all fragment
// loads via ldmatrix. A planes: packed [row][kp] ld ldA; W smem: [n][kp] ld 20.
template <int NT>
__device__ __forceinline__ void mma_chunk_ld(
    uint32_t aHi, uint32_t aLoD, int ldA, int aRow, int kpOff,
    uint32_t wHi, uint32_t wLoD, int cb,
    float4 (&acc)[2][NT], int lane) {
    int rsel = lane & 15;
    int csel = ((lane >> 4) & 1) << 2;
#pragma unroll
    for (int ks = 0; ks < 2; ks++) {
        uint32_t ah[2][4], al[2][4];
#pragma unroll
        for (int mt = 0; mt < 2; mt++) {
            uint32_t ad = aHi + (uint32_t)(((aRow + mt * 16 + rsel) * ldA
                                            + kpOff + ks * 8 + csel) << 2);
            ldsm_x4(ah[mt], ad);
            ldsm_x4(al[mt], ad + aLoD);
        }
#pragma unroll
        for (int np = 0; np < NT / 2; np++) {
            uint32_t bd = wHi + (uint32_t)(((cb + np * 16 + rsel) * 20
                                            + ks * 8 + csel) << 2);
            uint32_t bh[4], bl[4];
            ldsm_x4(bh, bd);
            ldsm_x4(bl, bd + wLoD);
#pragma unroll
            for (int mt = 0; mt < 2; mt++) {
                mma_bf(acc[mt][2 * np],     ah[mt], bh[0], bh[2]);
                mma_bf(acc[mt][2 * np],     ah[mt], bl[0], bl[2]);
                mma_bf(acc[mt][2 * np],     al[mt], bh[0], bh[2]);
                mma_bf(acc[mt][2 * np + 1], ah[mt], bh[1], bh[3]);
                mma_bf(acc[mt][2 * np + 1], ah[mt], bl[1], bl[3]);
                mma_bf(acc[mt][2 * np + 1], al[mt], bh[1], bh[3]);
            }
        }
    }
}

// ---------------- weight pre-split kernel (chunk-major output) ----------------
__global__ void k_prep(const float* __restrict__ W, uint32_t* __restrict__ dst,
                       int KP, int N, int srcStride, int dstStride) {
    int l = blockIdx.y;
    int idx = blockIdx.x * blockDim.x + threadIdx.x;
    if (idx >= KP * N) return;
    int kp = idx / N, n = idx - kp * N;
    const float* Ws = W + (size_t)l * srcStride;
    float w0 = Ws[(size_t)(2 * kp) * N + n];
    float w1 = Ws[(size_t)(2 * kp + 1) * N + n];
    uint32_t hi, lo;
    split2(w0, w1, hi, lo);
    uint32_t* hp = dst + (size_t)l * dstStride;
    size_t off = (size_t)(kp >> 4) * N * 16 + (size_t)n * 16 + (kp & 15);
    hp[off] = hi;
    hp[(size_t)KP * N + off] = lo;
}

// ---------------- index canonicalization ----------------
__global__ void k_detect(const void* __restrict__ ei) {
    if (threadIdx.x == 0) {
        const long long* p = (const long long*)ei;
        int ok = 1;
        for (int i = 0; i < 64; i++) {
            long long v = p[i];
            if (v < 0 || v >= NN) { ok = 0; break; }
        }
        g_is64 = ok;
    }
}

__global__ void k_convert(const void* __restrict__ ei) {
    int e = blockIdx.x * blockDim.x + threadIdx.x;
    if (e >= NE) return;
    int r, c;
    if (g_is64) {
        const long long* p = (const long long*)ei;
        r = (int)p[e]; c = (int)p[NE + e];
    } else {
        const int* p = (const int*)ei;
        r = p[e]; c = p[NE + e];
    }
    g_row[e] = r;
    g_col[e] = c;
    atomicAdd(&g_cnt[c], 1);
}

__global__ void k_inv() {
    int n = blockIdx.x * blockDim.x + threadIdx.x;
    if (n < NN) {
        g_inv[n] = 1.0f / fmaxf((float)g_cnt[n], 1.0f);
        g_cnt[n] = 0;
    }
}

// ---------------- encoders ----------------
__device__ __forceinline__ float warpsum(float s) {
#pragma unroll
    for (int o = 16; o; o >>= 1) s += __shfl_xor_sync(0xffffffffu, s, o);
    return s;
}

__global__ void k_enc(const float* __restrict__ x, const float* __restrict__ W,
                      const float* __restrict__ b, const float* __restrict__ g,
                      const float* __restrict__ be) {
    int n = blockIdx.x, j = threadIdx.x;
    __shared__ float sx[8];
    __shared__ float red[8];
    if (j < 7) sx[j] = x[n * 7 + j];
    __syncthreads();
    float a = b[j];
#pragma unroll
    for (int k = 0; k < 7; k++) a = fmaf(sx[k], W[k * HD + j], a);
    int w = j >> 5, lane = j & 31;
    float s = warpsum(a);
    if (lane == 0) red[w] = s;
    __syncthreads();
    float m = (red[0] + red[1] + red[2] + red[3]) * (1.0f / HD);
    float d = a - m;
    float q = warpsum(d * d);
    if (lane == 0) red[4 + w] = q;
    __syncthreads();
    float var = (red[4] + red[5] + red[6] + red[7]) * (1.0f / HD);
    float t = d * rsqrtf(var + 1e-5f) * g[j] + be[j];
    g_h[(size_t)n * HD + j] = gelu(t);
}

__global__ void k_ee(const float* __restrict__ ea, const float* __restrict__ W,
                     const float* __restrict__ b) {
    int e = blockIdx.x, j = threadIdx.x;
    __shared__ float sa[8];
    if (j < 8) sa[j] = ea[e * 8 + j];
    __syncthreads();
    float a = b[j];
#pragma unroll
    for (int k = 0; k < 8; k++) a = fmaf(sa[k], W[k * HD + j], a);
    g_ea[(size_t)e * HD + j] = a;
}

// ---------------- node projections P1 = h@W1a + b1, P2 = h@W1b ----------------
__global__ void __launch_bounds__(256, 2) k_P(int w1Off, const float* __restrict__ b1) {
    extern __shared__ float sm[];
    uint32_t* hHi = (uint32_t*)sm;          // 64 x 68
    uint32_t* hLo = hHi + 64 * 68;
    uint32_t* sWh = hHi + 8704;             // 256 x 20
    uint32_t* sWl = sWh + 5120;
    uint32_t smAddr = (uint32_t)__cvta_generic_to_shared(sm);
    uint32_t wHiA = smAddr + 8704u * 4;
    int tid = threadIdx.x, lane = tid & 31, wid = tid >> 5;
    int g = lane >> 2, tig = lane & 3;
    int base = blockIdx.x * 64;
    int part = blockIdx.y;
    const uint32_t* hiP = g_Wb + w1Off;
    const uint32_t* loP = hiP + 49152;   // 192*256

    float* out = part ? g_P2 : g_P1;

    for (int t = tid; t < 64 * 32; t += 256) {
        int i = t >> 5, q = t & 31;
        int n = base + i;
        float4 v = (n < NN) ? ((const float4*)g_h)[(size_t)n * 32 + q]
                            : make_float4(0, 0, 0, 0);
        uint32_t h0, l0, h1, l1;
        split2(v.x, v.y, h0, l0);
        split2(v.z, v.w, h1, l1);
        hHi[i * 68 + 2 * q] = h0; hHi[i * 68 + 2 * q + 1] = h1;
        hLo[i * 68 + 2 * q] = l0; hLo[i * 68 + 2 * q + 1] = l1;
    }

    int rowg = (wid >> 2) * 32;
    int cb1 = (wid & 3) * 64;
    float4 acc[2][8];
#pragma unroll
    for (int mt = 0; mt < 2; mt++)
#pragma unroll
        for (int nt = 0; nt < 8; nt++) acc[mt][nt] = make_float4(0, 0, 0, 0);
    for (int kc = 0; kc < 4; kc++) {
        __syncthreads();
        stageW(sWh, hiP + (size_t)(part * 4 + kc) * 4096, 256, tid);
        stageW(sWl, loP + (size_t)(part * 4 + kc) * 4096, 256, tid);
        __syncthreads();
        mma_chunk_ld<8>(smAddr, 17408u, 68, rowg, kc * 16,
                        wHiA, 20480u, cb1, acc, lane);
    }
#pragma unroll
    for (int mt = 0; mt < 2; mt++) {
        int r0 = base + rowg + mt * 16 + g;
#pragma unroll
        for (int nt = 0; nt < 8; nt++) {
            int C = cb1 + nt * 8 + 2 * tig;
            float bx = part ? 0.f : __ldg(&b1[C]);
            float by = part ? 0.f : __ldg(&b1[C + 1]);
            if (r0 < NN)
                *(float2*)&out[(size_t)r0 * 256 + C] =
                    make_float2(acc[mt][nt].x + bx, acc[mt][nt].y + by);
            if (r0 + 8 < NN)
                *(float2*)&out[(size_t)(r0 + 8) * 256 + C] =
                    make_float2(acc[mt][nt].z + bx, acc[mt][nt].w + by);
        }
    }
}

// ---------------- fused edge update ----------------
__global__ void __launch_bounds__(256, 2) k_edge(
    int w1Off, int w2Off,
    const float* __restrict__ g1, const float* __restrict__ bt1,
    const float* __restrict__ b2, const float* __restrict__ g2,
    const float* __restrict__ bt2) {
    extern __shared__ float sm[];
    uint32_t* buf = (uint32_t*)sm;
    uint32_t* eHi = buf;                 // 64 x 68 (GEMM1 A)
    uint32_t* eLo = buf + 64 * 68;
    uint32_t* tHi = buf;                 // 64 x 132 (GEMM2 A, aliased)
    uint32_t* tLo = buf + 64 * 132;
    uint32_t* sWh = buf + 16896;         // 256 x 20
    uint32_t* sWl = sWh + 5120;
    uint32_t smAddr = (uint32_t)__cvta_generic_to_shared(sm);
    uint32_t wHiA = smAddr + 16896u * 4;
    __shared__ int sRow[64], sCol[64];
    __shared__ __align__(16) float sRed[512];
    __shared__ float sP[896];
    int tid = threadIdx.x, lane = tid & 31, wid = tid >> 5;
    int g = lane >> 2, tig = lane & 3;
    int base = blockIdx.x * 64;
    const uint32_t* hi1 = g_Wb + w1Off;
    const uint32_t* lo1 = hi1 + 49152;
    const uint32_t* hi2 = g_Wb + w2Off;
    const uint32_t* lo2 = hi2 + 16384;

    if (tid < 64) { sRow[tid] = g_row[base + tid]; sCol[tid] = g_col[base + tid]; }
    for (int t = tid; t < 896; t += 256)
        sP[t] = (t < 256) ? g1[t] : (t < 512) ? bt1[t - 256]
              : (t < 640) ? b2[t - 512] : (t < 768) ? g2[t - 640] : bt2[t - 768];

    for (int t = tid; t < 64 * 32; t += 256) {   // ea tile -> packed bf16 planes
        int e = t >> 5, q = t & 31;
        float4 v = ((const float4*)g_ea)[(size_t)(base + e) * 32 + q];
        uint32_t h0, l0, h1, l1;
        split2(v.x, v.y, h0, l0);
        split2(v.z, v.w, h1, l1);
        eHi[e * 68 + 2 * q] = h0; eHi[e * 68 + 2 * q + 1] = h1;
        eLo[e * 68 + 2 * q] = l0; eLo[e * 68 + 2 * q + 1] = l1;
    }
    __syncthreads();   // sRow/sCol visible for gather

    int rowg = (wid >> 2) * 32;
    int cb1 = (wid & 3) * 64;
    int wcol = wid & 3;

    // GEMM1 acc init: per-fragment gather of P1[row] + P2[col]
    float4 acc[2][8];
#pragma unroll
    for (int mt = 0; mt < 2; mt++) {
        int r0 = rowg + mt * 16 + g, r1 = r0 + 8;
        const float* p1a = &g_P1[(size_t)sRow[r0] * 256];
        const float* p2a = &g_P2[(size_t)sCol[r0] * 256];
        const float* p1b = &g_P1[(size_t)sRow[r1] * 256];
        const float* p2b = &g_P2[(size_t)sCol[r1] * 256];
#pragma unroll
        for (int nt = 0; nt < 8; nt++) {
            int C = cb1 + nt * 8 + 2 * tig;
            float2 u1 = *(const float2*)&p1a[C];
            float2 u2 = *(const float2*)&p2a[C];
            float2 v1 = *(const float2*)&p1b[C];
            float2 v2 = *(const float2*)&p2b[C];
            acc[mt][nt] = make_float4(u1.x + u2.x, u1.y + u2.y,
                                      v1.x + v2.x, v1.y + v2.y);
        }
    }
    for (int kc = 0; kc < 4; kc++) {
        __syncthreads();
        stageW(sWh, hi1 + (size_t)(8 + kc) * 4096, 256, tid);
        stageW(sWl, lo1 + (size_t)(8 + kc) * 4096, 256, tid);
        __syncthreads();
        mma_chunk_ld<8>(smAddr, 17408u, 68, rowg, kc * 16,
                        wHiA, 20480u, cb1, acc, lane);
    }

    // LN(256) + GELU -> t (packed, aliased over eHi/eLo)
    {
        float p[2][2] = {{0, 0}, {0, 0}};
#pragma unroll
        for (int mt = 0; mt < 2; mt++)
#pragma unroll
            for (int nt = 0; nt < 8; nt++) {
                p[mt][0] += acc[mt][nt].x + acc[mt][nt].y;
                p[mt][1] += acc[mt][nt].z + acc[mt][nt].w;
            }
#pragma unroll
        for (int mt = 0; mt < 2; mt++)
#pragma unroll
            for (int h = 0; h < 2; h++) {
                p[mt][h] += __shfl_xor_sync(0xffffffffu, p[mt][h], 1);
                p[mt][h] += __shfl_xor_sync(0xffffffffu, p[mt][h], 2);
            }
        if (tig == 0)
#pragma unroll
            for (int mt = 0; mt < 2; mt++)
#pragma unroll
                for (int h = 0; h < 2; h++)
                    sRed[(rowg + mt * 16 + h * 8 + g) * 4 + wcol] = p[mt][h];
        __syncthreads();
        float m[2][2];
#pragma unroll
        for (int mt = 0; mt < 2; mt++)
#pragma unroll
            for (int h = 0; h < 2; h++) {
                float4 s = *(const float4*)&sRed[(rowg + mt * 16 + h * 8 + g) * 4];
                m[mt][h] = (s.x + s.y + s.z + s.w) * (1.0f / 256);
            }
        float q[2][2] = {{0, 0}, {0, 0}};
#pragma unroll
        for (int mt = 0; mt < 2; mt++)
#pragma unroll
            for (int nt = 0; nt < 8; nt++) {
                float dx = acc[mt][nt].x - m[mt][0], dy = acc[mt][nt].y - m[mt][0];
                float dz = acc[mt][nt].z - m[mt][1], dw = acc[mt][nt].w - m[mt][1];
                q[mt][0] += dx * dx + dy * dy;
                q[mt][1] += dz * dz + dw * dw;
            }
#pragma unroll
        for (int mt = 0; mt < 2; mt++)
#pragma unroll
            for (int h = 0; h < 2; h++) {
                q[mt][h] += __shfl_xor_sync(0xffffffffu, q[mt][h], 1);
                q[mt][h] += __shfl_xor_sync(0xffffffffu, q[mt][h], 2);
            }
        if (tig == 0)
#pragma unroll
            for (int mt = 0; mt < 2; mt++)
#pragma unroll
                for (int h = 0; h < 2; h++)
                    sRed[256 + (rowg + mt * 16 + h * 8 + g) * 4 + wcol] = q[mt][h];
        __syncthreads();
        float rn[2][2];
#pragma unroll
        for (int mt = 0; mt < 2; mt++)
#pragma unroll
            for (int h = 0; h < 2; h++) {
                float4 s = *(const float4*)&sRed[256 + (rowg + mt * 16 + h * 8 + g) * 4];
                rn[mt][h] = rsqrtf((s.x + s.y + s.z + s.w) * (1.0f / 256) + 1e-5f);
            }
#pragma unroll
        for (int mt = 0; mt < 2; mt++) {
            int r0 = rowg + mt * 16 + g;
#pragma unroll
            for (int nt = 0; nt < 8; nt++) {
                int C = cb1 + nt * 8 + 2 * tig;
                int cp = C >> 1;
                float gx = sP[C], gy = sP[C + 1];
                float bx = sP[256 + C], by = sP[256 + C + 1];
                float tx = gelu((acc[mt][nt].x - m[mt][0]) * rn[mt][0] * gx + bx);
                float ty = gelu((acc[mt][nt].y - m[mt][0]) * rn[mt][0] * gy + by);
                float tz = gelu((acc[mt][nt].z - m[mt][1]) * rn[mt][1] * gx + bx);
                float tw = gelu((acc[mt][nt].w - m[mt][1]) * rn[mt][1] * gy + by);
                uint32_t h0, l0, h1, l1;
                split2(tx, ty, h0, l0);
                split2(tz, tw, h1, l1);
                tHi[r0 * 132 + cp] = h0; tLo[r0 * 132 + cp] = l0;
                tHi[(r0 + 8) * 132 + cp] = h1; tLo[(r0 + 8) * 132 + cp] = l1;
            }
        }
    }

    // GEMM2: t @ W2  (M=64, N=128, K=256)
    int cb2 = (wid & 3) * 32;
    float4 acc2[2][4];
#pragma unroll
    for (int mt = 0; mt < 2; mt++)
#pragma unroll
        for (int nt = 0; nt < 4; nt++) acc2[mt][nt] = make_float4(0, 0, 0, 0);
    for (int kc = 0; kc < 8; kc++) {
        __syncthreads();
        stageW(sWh, hi2 + (size_t)kc * 2048, 128, tid);
        stageW(sWl, lo2 + (size_t)kc * 2048, 128, tid);
        __syncthreads();
        mma_chunk_ld<4>(smAddr, 33792u, 132, rowg, kc * 16,
                        wHiA, 20480u, cb2, acc2, lane);
    }

    // + b2, LN(128), residual (re-read g_ea), store + scatter
    {
#pragma unroll
        for (int mt = 0; mt < 2; mt++)
#pragma unroll
            for (int nt = 0; nt < 4; nt++) {
                int C = cb2 + nt * 8 + 2 * tig;
                acc2[mt][nt].x += sP[512 + C]; acc2[mt][nt].y += sP[512 + C + 1];
                acc2[mt][nt].z += sP[512 + C]; acc2[mt][nt].w += sP[512 + C + 1];
            }
        float p[2][2] = {{0, 0}, {0, 0}};
#pragma unroll
        for (int mt = 0; mt < 2; mt++)
#pragma unroll
            for (int nt = 0; nt < 4; nt++) {
                p[mt][0] += acc2[mt][nt].x + acc2[mt][nt].y;
                p[mt][1] += acc2[mt][nt].z + acc2[mt][nt].w;
            }
#pragma unroll
        for (int mt = 0; mt < 2; mt++)
#pragma unroll
            for (int h = 0; h < 2; h++) {
                p[mt][h] += __shfl_xor_sync(0xffffffffu, p[mt][h], 1);
                p[mt][h] += __shfl_xor_sync(0xffffffffu, p[mt][h], 2);
            }
        if (tig == 0)
#pragma unroll
            for (int mt = 0; mt < 2; mt++)
#pragma unroll
                for (int h = 0; h < 2; h++)
                    sRed[(rowg + mt * 16 + h * 8 + g) * 4 + wcol] = p[mt][h];
        __syncthreads();
        float m[2][2];
#pragma unroll
        for (int mt = 0; mt < 2; mt++)
#pragma unroll
            for (int h = 0; h < 2; h++) {
                float4 s = *(const float4*)&sRed[(rowg + mt * 16 + h * 8 + g) * 4];
                m[mt][h] = (s.x + s.y + s.z + s.w) * (1.0f / 128);
            }
        float q[2][2] = {{0, 0}, {0, 0}};
#pragma unroll
        for (int mt = 0; mt < 2; mt++)
#pragma unroll
            for (int nt = 0; nt < 4; nt++) {
                float dx = acc2[mt][nt].x - m[mt][0], dy = acc2[mt][nt].y - m[mt][0];
                float dz = acc2[mt][nt].z - m[mt][1], dw = acc2[mt][nt].w - m[mt][1];
                q[mt][0] += dx * dx + dy * dy;
                q[mt][1] += dz * dz + dw * dw;
            }
#pragma unroll
        for (int mt = 0; mt < 2; mt++)
#pragma unroll
            for (int h = 0; h < 2; h++) {
                q[mt][h] += __shfl_xor_sync(0xffffffffu, q[mt][h], 1);
                q[mt][h] += __shfl_xor_sync(0xffffffffu, q[mt][h], 2);
            }
        if (tig == 0)
#pragma unroll
            for (int mt = 0; mt < 2; mt++)
#pragma unroll
                for (int h = 0; h < 2; h++)
                    sRed[256 + (rowg + mt * 16 + h * 8 + g) * 4 + wcol] = q[mt][h];
        __syncthreads();
        float rn[2][2];
#pragma unroll
        for (int mt = 0; mt < 2; mt++)
#pragma unroll
            for (int h = 0; h < 2; h++) {
                float4 s = *(const float4*)&sRed[256 + (rowg + mt * 16 + h * 8 + g) * 4];
                rn[mt][h] = rsqrtf((s.x + s.y + s.z + s.w) * (1.0f / 128) + 1e-5f);
            }
#pragma unroll
        for (int mt = 0; mt < 2; mt++) {
            int r0 = rowg + mt * 16 + g;
            int r1 = r0 + 8;
#pragma unroll
            for (int nt = 0; nt < 4; nt++) {
                int C = cb2 + nt * 8 + 2 * tig;
                float gx = sP[640 + C], gy = sP[640 + C + 1];
                float bx = sP[768 + C], by = sP[768 + C + 1];
                float2 e0 = *(const float2*)&g_ea[(size_t)(base + r0) * HD + C];
                float2 e1 = *(const float2*)&g_ea[(size_t)(base + r1) * HD + C];
                float ox = e0.x + (acc2[mt][nt].x - m[mt][0]) * rn[mt][0] * gx + bx;
                float oy = e0.y + (acc2[mt][nt].y - m[mt][0]) * rn[mt][0] * gy + by;
                float oz = e1.x + (acc2[mt][nt].z - m[mt][1]) * rn[mt][1] * gx + bx;
                float ow = e1.y + (acc2[mt][nt].w - m[mt][1]) * rn[mt][1] * gy + by;
                *(float2*)&g_ea[(size_t)(base + r0) * HD + C] = make_float2(ox, oy);
                *(float2*)&g_ea[(size_t)(base + r1) * HD + C] = make_float2(oz, ow);
                float* a0 = &g_agg[(size_t)sCol[r0] * HD + C];
                float* a1 = &g_agg[(size_t)sCol[r1] * HD + C];
                asm volatile("red.global.add.v2.f32 [%0], {%1,%2};"
                             :: "l"(a0), "f"(ox), "f"(oy) : "memory");
                asm volatile("red.global.add.v2.f32 [%0], {%1,%2};"
                             :: "l"(a1), "f"(oz), "f"(ow) : "memory");
            }
        }
    }
}

// ---------------- fused node update ----------------
__global__ void __launch_bounds__(256, 2) k_node(
    int w1Off, int w2Off,
    const float* __restrict__ b1, const float* __restrict__ g1,
    const float* __restrict__ bt1, const float* __restrict__ b2,
    const float* __restrict__ g2, const float* __restrict__ bt2) {
    extern __shared__ float sm[];
    uint32_t* aHi = (uint32_t*)sm;            // 64 x 132 packed (K=256)
    uint32_t* aLo = aHi + 64 * 132;
    uint32_t* sWh = aHi + 16896;              // 256 x 20
    uint32_t* sWl = sWh + 5120;
    uint32_t* tHi = aHi;                      // alias after GEMM1
    uint32_t* tLo = aLo;
    uint32_t smAddr = (uint32_t)__cvta_generic_to_shared(sm);
    uint32_t wHiA = smAddr + 16896u * 4;
    __shared__ __align__(16) float sRed[512];
    __shared__ float sP[1152];
    int tid = threadIdx.x, lane = tid & 31, wid = tid >> 5;
    int g = lane >> 2, tig = lane & 3;
    int base = blockIdx.x * 64;
    const uint32_t* hi1 = g_Wb + w1Off;
    const uint32_t* lo1 = hi1 + 32768;
    const uint32_t* hi2 = g_Wb + w2Off;
    const uint32_t* lo2 = hi2 + 16384;

    for (int t = tid; t < 1152; t += 256)
        sP[t] = (t < 256) ? b1[t] : (t < 512) ? g1[t - 256] : (t < 768) ? bt1[t - 512]
              : (t < 896) ? b2[t - 768] : (t < 1024) ? g2[t - 896] : bt2[t - 1024];

    for (int t = tid; t < 64 * 32; t += 256) {   // h -> packed cols 0..63
        int i = t >> 5, q = t & 31;
        int n = base + i;
        float4 v = (n < NN) ? ((const float4*)g_h)[(size_t)n * 32 + q]
                            : make_float4(0, 0, 0, 0);
        uint32_t h0, l0, h1, l1;
        split2(v.x, v.y, h0, l0);
        split2(v.z, v.w, h1, l1);
        aHi[i * 132 + 2 * q] = h0; aHi[i * 132 + 2 * q + 1] = h1;
        aLo[i * 132 + 2 * q] = l0; aLo[i * 132 + 2 * q + 1] = l1;
    }
    for (int t = tid; t < 64 * 32; t += 256) {   // agg*inv -> packed cols 64..127
        int i = t >> 5, q = t & 31;
        int n = base + i;
        float4 v = make_float4(0, 0, 0, 0);
        if (n < NN) {
            float4* ap = (float4*)&g_agg[(size_t)n * HD + q * 4];
            v = *ap;
            float iv = g_inv[n];
            v.x *= iv; v.y *= iv; v.z *= iv; v.w *= iv;
            *ap = make_float4(0, 0, 0, 0);
        }
        uint32_t h0, l0, h1, l1;
        split2(v.x, v.y, h0, l0);
        split2(v.z, v.w, h1, l1);
        aHi[i * 132 + 64 + 2 * q] = h0; aHi[i * 132 + 64 + 2 * q + 1] = h1;
        aLo[i * 132 + 64 + 2 * q] = l0; aLo[i * 132 + 64 + 2 * q + 1] = l1;
    }
    __syncthreads();

    int rowg = (wid >> 2) * 32;
    int cb1 = (wid & 3) * 64;
    int wcol = wid & 3;

    // GEMM1 (M=64, N=256, K=256), acc init = b1
    float4 acc[2][8];
#pragma unroll
    for (int mt = 0; mt < 2; mt++)
#pragma unroll
        for (int nt = 0; nt < 8; nt++) {
            int C = cb1 + nt * 8 + 2 * tig;
            acc[mt][nt] = make_float4(sP[C], sP[C + 1], sP[C], sP[C + 1]);
        }
    for (int kc = 0; kc < 8; kc++) {
        __syncthreads();
        stageW(sWh, hi1 + (size_t)kc * 4096, 256, tid);
        stageW(sWl, lo1 + (size_t)kc * 4096, 256, tid);
        __syncthreads();
        mma_chunk_ld<8>(smAddr, 33792u, 132, rowg, kc * 16,
                        wHiA, 20480u, cb1, acc, lane);
    }

    // LN(256) + GELU -> t packed (aliased on A)
    {
        float p[2][2] = {{0, 0}, {0, 0}};
#pragma unroll
        for (int mt = 0; mt < 2; mt++)
#pragma unroll
            for (int nt = 0; nt < 8; nt++) {
                p[mt][0] += acc[mt][nt].x + acc[mt][nt].y;
                p[mt][1] += acc[mt][nt].z + acc[mt][nt].w;
            }
#pragma unroll
        for (int mt = 0; mt < 2; mt++)
#pragma unroll
            for (int h = 0; h < 2; h++) {
                p[mt][h] += __shfl_xor_sync(0xffffffffu, p[mt][h], 1);
                p[mt][h] += __shfl_xor_sync(0xffffffffu, p[mt][h], 2);
            }
        if (tig == 0)
#pragma unroll
            for (int mt = 0; mt < 2; mt++)
#pragma unroll
                for (int h = 0; h < 2; h++)
                    sRed[(rowg + mt * 16 + h * 8 + g) * 4 + wcol] = p[mt][h];
        __syncthreads();
        float m[2][2];
#pragma unroll
        for (int mt = 0; mt < 2; mt++)
#pragma unroll
            for (int h = 0; h < 2; h++) {
                float4 s = *(const float4*)&sRed[(rowg + mt * 16 + h * 8 + g) * 4];
                m[mt][h] = (s.x + s.y + s.z + s.w) * (1.0f / 256);
            }
        float q[2][2] = {{0, 0}, {0, 0}};
#pragma unroll
        for (int mt = 0; mt < 2; mt++)
#pragma unroll
            for (int nt = 0; nt < 8; nt++) {
                float dx = acc[mt][nt].x - m[mt][0], dy = acc[mt][nt].y - m[mt][0];
                float dz = acc[mt][nt].z - m[mt][1], dw = acc[mt][nt].w - m[mt][1];
                q[mt][0] += dx * dx + dy * dy;
                q[mt][1] += dz * dz + dw * dw;
            }
#pragma unroll
        for (int mt = 0; mt < 2; mt++)
#pragma unroll
            for (int h = 0; h < 2; h++) {
                q[mt][h] += __shfl_xor_sync(0xffffffffu, q[mt][h], 1);
                q[mt][h] += __shfl_xor_sync(0xffffffffu, q[mt][h], 2);
            }
        if (tig == 0)
#pragma unroll
            for (int mt = 0; mt < 2; mt++)
#pragma unroll
                for (int h = 0; h < 2; h++)
                    sRed[256 + (rowg + mt * 16 + h * 8 + g) * 4 + wcol] = q[mt][h];
        __syncthreads();
        float rn[2][2];
#pragma unroll
        for (int mt = 0; mt < 2; mt++)
#pragma unroll
            for (int h = 0; h < 2; h++) {
                float4 s = *(const float4*)&sRed[256 + (rowg + mt * 16 + h * 8 + g) * 4];
                rn[mt][h] = rsqrtf((s.x + s.y + s.z + s.w) * (1.0f / 256) + 1e-5f);
            }
#pragma unroll
        for (int mt = 0; mt < 2; mt++) {
            int r0 = rowg + mt * 16 + g;
#pragma unroll
            for (int nt = 0; nt < 8; nt++) {
                int C = cb1 + nt * 8 + 2 * tig;
                int cp = C >> 1;
                float gx = sP[256 + C], gy = sP[256 + C + 1];
                float bx = sP[512 + C], by = sP[512 + C + 1];
                float tx = gelu((acc[mt][nt].x - m[mt][0]) * rn[mt][0] * gx + bx);
                float ty = gelu((acc[mt][nt].y - m[mt][0]) * rn[mt][0] * gy + by);
                float tz = gelu((acc[mt][nt].z - m[mt][1]) * rn[mt][1] * gx + bx);
                float tw = gelu((acc[mt][nt].w - m[mt][1]) * rn[mt][1] * gy + by);
                uint32_t h0, l0, h1, l1;
                split2(tx, ty, h0, l0);
                split2(tz, tw, h1, l1);
                tHi[r0 * 132 + cp] = h0; tLo[r0 * 132 + cp] = l0;
                tHi[(r0 + 8) * 132 + cp] = h1; tLo[(r0 + 8) * 132 + cp] = l1;
            }
        }
    }

    // GEMM2 (M=64, N=128, K=256)
    int cb2 = (wid & 3) * 32;
    float4 acc2[2][4];
#pragma unroll
    for (int mt = 0; mt < 2; mt++)
#pragma unroll
        for (int nt = 0; nt < 4; nt++) acc2[mt][nt] = make_float4(0, 0, 0, 0);
    for (int kc = 0; kc < 8; kc++) {
        __syncthreads();
        stageW(sWh, hi2 + (size_t)kc * 2048, 128, tid);
        stageW(sWl, lo2 + (size_t)kc * 2048, 128, tid);
        __syncthreads();
        mma_chunk_ld<4>(smAddr, 33792u, 132, rowg, kc * 16,
                        wHiA, 20480u, cb2, acc2, lane);
    }

    // + b2, LN(128), residual from g_h, store h
    {
#pragma unroll
        for (int mt = 0; mt < 2; mt++)
#pragma unroll
            for (int nt = 0; nt < 4; nt++) {
                int C = cb2 + nt * 8 + 2 * tig;
                acc2[mt][nt].x += sP[768 + C]; acc2[mt][nt].y += sP[768 + C + 1];
                acc2[mt][nt].z += sP[768 + C]; acc2[mt][nt].w += sP[768 + C + 1];
            }
        float p[2][2] = {{0, 0}, {0, 0}};
#pragma unroll
        for (int mt = 0; mt < 2; mt++)
#pragma unroll
            for (int nt = 0; nt < 4; nt++) {
                p[mt][0] += acc2[mt][nt].x + acc2[mt][nt].y;
                p[mt][1] += acc2[mt][nt].z + acc2[mt][nt].w;
            }
#pragma unroll
        for (int mt = 0; mt < 2; mt++)
#pragma unroll
            for (int h = 0; h < 2; h++) {
                p[mt][h] += __shfl_xor_sync(0xffffffffu, p[mt][h], 1);
                p[mt][h] += __shfl_xor_sync(0xffffffffu, p[mt][h], 2);
            }
        if (tig == 0)
#pragma unroll
            for (int mt = 0; mt < 2; mt++)
#pragma unroll
                for (int h = 0; h < 2; h++)
                    sRed[(rowg + mt * 16 + h * 8 + g) * 4 + wcol] = p[mt][h];
        __syncthreads();
        float m[2][2];
#pragma unroll
        for (int mt = 0; mt < 2; mt++)
#pragma unroll
            for (int h = 0; h < 2; h++) {
                float4 s = *(const float4*)&sRed[(rowg + mt * 16 + h * 8 + g) * 4];
                m[mt][h] = (s.x + s.y + s.z + s.w) * (1.0f / 128);
            }
        float q[2][2] = {{0, 0}, {0, 0}};
#pragma unroll
        for (int mt = 0; mt < 2; mt++)
#pragma unroll
            for (int nt = 0; nt < 4; nt++) {
                float dx = acc2[mt][nt].x - m[mt][0], dy = acc2[mt][nt].y - m[mt][0];
                float dz = acc2[mt][nt].z - m[mt][1], dw = acc2[mt][nt].w - m[mt][1];
                q[mt][0] += dx * dx + dy * dy;
                q[mt][1] += dz * dz + dw * dw;
            }
#pragma unroll
        for (int mt = 0; mt < 2; mt++)
#pragma unroll
            for (int h = 0; h < 2; h++) {
                q[mt][h] += __shfl_xor_sync(0xffffffffu, q[mt][h], 1);
                q[mt][h] += __shfl_xor_sync(0xffffffffu, q[mt][h], 2);
            }
        if (tig == 0)
#pragma unroll
            for (int mt = 0; mt < 2; mt++)
#pragma unroll
                for (int h = 0; h < 2; h++)
                    sRed[256 + (rowg + mt * 16 + h * 8 + g) * 4 + wcol] = q[mt][h];
        __syncthreads();
        float rn[2][2];
#pragma unroll
        for (int mt = 0; mt < 2; mt++)
#pragma unroll
            for (int h = 0; h < 2; h++) {
                float4 s = *(const float4*)&sRed[256 + (rowg + mt * 16 + h * 8 + g) * 4];
                rn[mt][h] = rsqrtf((s.x + s.y + s.z + s.w) * (1.0f / 128) + 1e-5f);
            }
#pragma unroll
        for (int mt = 0; mt < 2; mt++) {
            int r0 = rowg + mt * 16 + g;
            int r1 = r0 + 8;
            int n0 = base + r0, n1 = base + r1;
#pragma unroll
            for (int nt = 0; nt < 4; nt++) {
                int C = cb2 + nt * 8 + 2 * tig;
                float gx = sP[896 + C], gy = sP[896 + C + 1];
                float bx = sP[1024 + C], by = sP[1024 + C + 1];
                if (n0 < NN) {
                    float2 hr = *(const float2*)&g_h[(size_t)n0 * HD + C];
                    float ox = hr.x + (acc2[mt][nt].x - m[mt][0]) * rn[mt][0] * gx + bx;
                    float oy = hr.y + (acc2[mt][nt].y - m[mt][0]) * rn[mt][0] * gy + by;
                    *(float2*)&g_h[(size_t)n0 * HD + C] = make_float2(ox, oy);
                }
                if (n1 < NN) {
                    float2 hr = *(const float2*)&g_h[(size_t)n1 * HD + C];
                    float oz = hr.x + (acc2[mt][nt].z - m[mt][1]) * rn[mt][1] * gx + bx;
                    float ow = hr.y + (acc2[mt][nt].w - m[mt][1]) * rn[mt][1] * gy + by;
                    *(float2*)&g_h[(size_t)n1 * HD + C] = make_float2(oz, ow);
                }
            }
        }
    }
}

// ---------------- decoder ----------------
__global__ void k_dec(const float* __restrict__ W1, const float* __restrict__ b1,
                      const float* __restrict__ W2, const float* __restrict__ b2,
                      float* __restrict__ out) {
    int n = blockIdx.x, j = threadIdx.x;
    __shared__ float sh[128];
    __shared__ float st[128];
    sh[j] = g_h[(size_t)n * HD + j];
    __syncthreads();
    float a = b1[j];
#pragma unroll 8
    for (int k = 0; k < 128; k++) a = fmaf(sh[k], W1[k * HD + j], a);
    st[j] = gelu(a);
    __syncthreads();
    int w = j >> 5, lane = j & 31;
    float s = 0;
#pragma unroll
    for (int k = lane; k < 128; k += 32) s = fmaf(st[k], W2[k * 4 + w], s);
    s = warpsum(s);
    if (lane == 0) out[(size_t)n * 4 + w] = s + b2[w];
}

// ---------------- launch ----------------
extern "C" void kernel_launch(void* const* d_in, const int* in_sizes, int n_in,
                              void* d_out, int out_size) {
    (void)in_sizes; (void)n_in; (void)out_size;
    const float* x       = (const float*)d_in[0];
    const void*  ei      = d_in[1];
    const float* eattr   = (const float*)d_in[2];
    const float* enc_W   = (const float*)d_in[3];
    const float* enc_b   = (const float*)d_in[4];
    const float* enc_g   = (const float*)d_in[5];
    const float* enc_bt  = (const float*)d_in[6];
    const float* ee_W    = (const float*)d_in[7];
    const float* ee_b    = (const float*)d_in[8];
    const float* eW1     = (const float*)d_in[9];
    const float* eb1     = (const float*)d_in[10];
    const float* eg1     = (const float*)d_in[11];
    const float* ebt1    = (const float*)d_in[12];
    const float* eW2     = (const float*)d_in[13];
    const float* eb2     = (const float*)d_in[14];
    const float* eg2     = (const float*)d_in[15];
    const float* ebt2    = (const float*)d_in[16];
    const float* nW1     = (const float*)d_in[17];
    const float* nb1     = (const float*)d_in[18];
    const float* ng1     = (const float*)d_in[19];
    const float* nbt1    = (const float*)d_in[20];
    const float* nW2     = (const float*)d_in[21];
    const float* nb2     = (const float*)d_in[22];
    const float* ng2     = (const float*)d_in[23];
    const float* nbt2    = (const float*)d_in[24];
    const float* dec_W1  = (const float*)d_in[25];
    const float* dec_b1  = (const float*)d_in[26];
    const float* dec_W2  = (const float*)d_in[27];
    const float* dec_b2  = (const float*)d_in[28];

    cudaFuncSetAttribute(k_edge, cudaFuncAttributeMaxDynamicSharedMemorySize, EDGE_SMEM);
    cudaFuncSetAttribute(k_node, cudaFuncAttributeMaxDynamicSharedMemorySize, NODE_SMEM);
    cudaFuncSetAttribute(k_P,    cudaFuncAttributeMaxDynamicSharedMemorySize, P_SMEM);

    // pre-split weights into packed bf16 hi/lo planes, chunk-major (once per launch)
    {
        uint32_t* wb = nullptr;
        cudaGetSymbolAddress((void**)&wb, g_Wb);
        k_prep<<<dim3(192, 10), 256>>>(eW1, wb + EW1_OFF, 192, 256, 98304, 98304);
        k_prep<<<dim3(64, 10), 256>>>(eW2, wb + EW2_OFF, 128, 128, 32768, 32768);
        k_prep<<<dim3(128, 10), 256>>>(nW1, wb + NW1_OFF, 128, 256, 65536, 65536);
        k_prep<<<dim3(64, 10), 256>>>(nW2, wb + NW2_OFF, 128, 128, 32768, 32768);
    }

    k_detect<<<1, 32>>>(ei);
    k_convert<<<(NE + 255) / 256, 256>>>(ei);
    k_inv<<<(NN + 255) / 256, 256>>>();
    k_enc<<<NN, 128>>>(x, enc_W, enc_b, enc_g, enc_bt);
    k_ee<<<NE, 128>>>(eattr, ee_W, ee_b);

    const int nodeBlocks = (NN + 63) / 64;  // 782
    for (int l = 0; l < 10; l++) {
        k_P<<<dim3(nodeBlocks, 2), 256, P_SMEM>>>(EW1_OFF + l * 98304, eb1 + l * 256);
        k_edge<<<NE / 64, 256, EDGE_SMEM>>>(
            EW1_OFF + l * 98304, EW2_OFF + l * 32768,
            eg1 + l * 256, ebt1 + l * 256,
            eb2 + l * 128, eg2 + l * 128, ebt2 + l * 128);
        k_node<<<nodeBlocks, 256, NODE_SMEM>>>(
            NW1_OFF + l * 65536, NW2_OFF + l * 32768,
            nb1 + l * 256, ng1 + l * 256, nbt1 + l * 256,
            nb2 + l * 128, ng2 + l * 128, nbt2 + l * 128);
    }
    k_dec<<<NN, 128>>>(dec_W1, dec_b1, dec_W2, dec_b2, (float*)d_out);
}

// round 8
// speedup vs baseline: 1.0864x; 1.0864x over previous
#include <cuda_runtime.h>
#include <cuda_bf16.h>
#include <cstdint>

#define NN 50000
#define NE 600000
#define HD 128

#define EDGE_SMEM 101376   // (16896 + 8448) u32 * 4
#define NODE_SMEM 101376
#define P_SMEM    68096    // (2*64*68 + 2*16*260)*4

// packed-weight plane offsets in g_Wb (uint32 units)
#define EW1_OFF 0          // per layer 2*192*256 = 98304
#define EW2_OFF 983040     // per layer 2*128*128 = 32768
#define NW1_OFF 1310720    // per layer 2*128*256 = 65536
#define NW2_OFF 1966080    // per layer 32768
#define WB_TOTAL 2293760

// ---------------- device scratch ----------------
__device__ float g_h[NN * HD];
__device__ float g_ea[(size_t)NE * HD];
__device__ float g_P1[(size_t)NN * 256];
__device__ float g_P2[(size_t)NN * 256];
__device__ float g_agg[NN * HD];
__device__ float g_inv[NN];
__device__ int   g_cnt[NN];
__device__ int   g_row[NE];
__device__ int   g_col[NE];
__device__ int   g_is64;
__device__ uint32_t g_Wb[WB_TOTAL];

// ---------------- helpers ----------------
__device__ __forceinline__ float gelu(float x) { return x * normcdff(x); }

__device__ __forceinline__ uint32_t pack2(float a, float b) {
    uint32_t r;
    asm("cvt.rn.bf16x2.f32 %0, %1, %2;" : "=r"(r) : "f"(b), "f"(a));
    return r;
}

__device__ __forceinline__ void split2(float a, float b, uint32_t& hi, uint32_t& lo) {
    hi = pack2(a, b);
    float ra = a - __uint_as_float(hi << 16);
    float rb = b - __uint_as_float(hi & 0xffff0000u);
    lo = pack2(ra, rb);
}

__device__ __forceinline__ void mma_bf(float4& d, const uint32_t* a,
                                       uint32_t b0, uint32_t b1) {
    asm("mma.sync.aligned.m16n8k16.row.col.f32.bf16.bf16.f32 "
        "{%0,%1,%2,%3},{%4,%5,%6,%7},{%8,%9},{%0,%1,%2,%3};"
        : "+f"(d.x), "+f"(d.y), "+f"(d.z), "+f"(d.w)
        : "r"(a[0]), "r"(a[1]), "r"(a[2]), "r"(a[3]), "r"(b0), "r"(b1));
}

// Stage 16 packed-k rows x N cols of hi/lo weight planes into smem (ld given).
__device__ __forceinline__ void stage16(uint32_t* sWh, uint32_t* sWl,
                                        const uint32_t* __restrict__ hiP,
                                        const uint32_t* __restrict__ loP,
                                        int kpBase, int N, int ld, int tid) {
    int q4n = N >> 2;
    for (int t = tid; t < 16 * q4n; t += 256) {
        int r = t / q4n, q = t - r * q4n;
        *(uint4*)&sWh[r * ld + q * 4] = *(const uint4*)&hiP[(size_t)(kpBase + r) * N + q * 4];
        *(uint4*)&sWl[r * ld + q * 4] = *(const uint4*)&loP[(size_t)(kpBase + r) * N + q * 4];
    }
}

// Stage 32 packed-k rows x 128 cols (GEMM2 weights), ld 132.
__device__ __forceinline__ void stage32n128(uint32_t* sWh, uint32_t* sWl,
                                            const uint32_t* __restrict__ hiP,
                                            const uint32_t* __restrict__ loP,
                                            int kpBase, int tid) {
    for (int t = tid; t < 32 * 32; t += 256) {
        int r = t >> 5, q = t & 31;
        *(uint4*)&sWh[r * 132 + q * 4] = *(const uint4*)&hiP[(size_t)(kpBase + r) * 128 + q * 4];
        *(uint4*)&sWl[r * 132 + q * 4] = *(const uint4*)&loP[(size_t)(kpBase + r) * 128 + q * 4];
    }
}

// One k32 chunk (two m16n8k16 steps), 3-term bf16-split MMA.
template <int NT>
__device__ __forceinline__ void mma_chunk_bf(
    const uint32_t* sAh, const uint32_t* sAl, int ldA, int aRow, int kpOff,
    const uint32_t* sWh, const uint32_t* sWl, int ldW, int cb,
    float4 (&acc)[2][NT], int lane) {
    int g = lane >> 2, tig = lane & 3;
#pragma unroll
    for (int ks = 0; ks < 2; ks++) {
        int cbase = kpOff + ks * 8;
        uint32_t ah[2][4], al[2][4];
#pragma unroll
        for (int mt = 0; mt < 2; mt++) {
            int r0 = aRow + mt * 16 + g, r1 = r0 + 8;
            ah[mt][0] = sAh[r0 * ldA + cbase + tig];
            ah[mt][1] = sAh[r1 * ldA + cbase + tig];
            ah[mt][2] = sAh[r0 * ldA + cbase + tig + 4];
            ah[mt][3] = sAh[r1 * ldA + cbase + tig + 4];
            al[mt][0] = sAl[r0 * ldA + cbase + tig];
            al[mt][1] = sAl[r1 * ldA + cbase + tig];
            al[mt][2] = sAl[r0 * ldA + cbase + tig + 4];
            al[mt][3] = sAl[r1 * ldA + cbase + tig + 4];
        }
        int wr0 = ks * 8 + tig, wr1 = wr0 + 4;
#pragma unroll
        for (int nt = 0; nt < NT; nt++) {
            int n = cb + nt * 8 + g;
            uint32_t bh0 = sWh[wr0 * ldW + n], bh1 = sWh[wr1 * ldW + n];
            uint32_t bl0 = sWl[wr0 * ldW + n], bl1 = sWl[wr1 * ldW + n];
#pragma unroll
            for (int mt = 0; mt < 2; mt++) {
                mma_bf(acc[mt][nt], ah[mt], bh0, bh1);
                mma_bf(acc[mt][nt], ah[mt], bl0, bl1);
                mma_bf(acc[mt][nt], al[mt], bh0, bh1);
            }
        }
    }
}

// ---------------- fused weight pre-split (all 4 groups, one launch) ----------------
__global__ void k_prepAll(const float* __restrict__ eW1, const float* __restrict__ eW2,
                          const float* __restrict__ nW1, const float* __restrict__ nW2,
                          uint32_t* __restrict__ wb) {
    int l = blockIdx.y;
    int idx = blockIdx.x * 256 + threadIdx.x;   // < 114688
    const float* W;
    uint32_t* hp;
    int KP, N, rel;
    if (idx < 49152)      { rel = idx;          W = eW1 + (size_t)l * 98304; hp = wb + EW1_OFF + l * 98304; KP = 192; N = 256; }
    else if (idx < 65536) { rel = idx - 49152;  W = eW2 + (size_t)l * 32768; hp = wb + EW2_OFF + l * 32768; KP = 128; N = 128; }
    else if (idx < 98304) { rel = idx - 65536;  W = nW1 + (size_t)l * 65536; hp = wb + NW1_OFF + l * 65536; KP = 128; N = 256; }
    else                  { rel = idx - 98304;  W = nW2 + (size_t)l * 32768; hp = wb + NW2_OFF + l * 32768; KP = 128; N = 128; }
    int kp = rel / N, n = rel - kp * N;
    float w0 = W[(size_t)(2 * kp) * N + n];
    float w1 = W[(size_t)(2 * kp + 1) * N + n];
    uint32_t hi, lo;
    split2(w0, w1, hi, lo);
    hp[(size_t)kp * N + n] = hi;
    hp[(size_t)KP * N + (size_t)kp * N + n] = lo;
}

// ---------------- index canonicalization ----------------
__global__ void k_detect(const void* __restrict__ ei) {
    if (threadIdx.x == 0) {
        const long long* p = (const long long*)ei;
        int ok = 1;
        for (int i = 0; i < 64; i++) {
            long long v = p[i];
            if (v < 0 || v >= NN) { ok = 0; break; }
        }
        g_is64 = ok;
    }
}

__global__ void k_convert(const void* __restrict__ ei) {
    int e = blockIdx.x * blockDim.x + threadIdx.x;
    if (e >= NE) return;
    int r, c;
    if (g_is64) {
        const long long* p = (const long long*)ei;
        r = (int)p[e]; c = (int)p[NE + e];
    } else {
        const int* p = (const int*)ei;
        r = p[e]; c = p[NE + e];
    }
    g_row[e] = r;
    g_col[e] = c;
    atomicAdd(&g_cnt[c], 1);
}

__global__ void k_inv() {
    int n = blockIdx.x * blockDim.x + threadIdx.x;
    if (n < NN) {
        g_inv[n] = 1.0f / fmaxf((float)g_cnt[n], 1.0f);
        g_cnt[n] = 0;
    }
}

// ---------------- fused encoders (node blocks then edge blocks) ----------------
__device__ __forceinline__ float warpsum(float s) {
#pragma unroll
    for (int o = 16; o; o >>= 1) s += __shfl_xor_sync(0xffffffffu, s, o);
    return s;
}

__global__ void k_encee(const float* __restrict__ x, const float* __restrict__ encW,
                        const float* __restrict__ encb, const float* __restrict__ encg,
                        const float* __restrict__ encbt,
                        const float* __restrict__ eattr, const float* __restrict__ eeW,
                        const float* __restrict__ eeb) {
    __shared__ float sx[8];
    __shared__ float red[8];
    int j = threadIdx.x;
    if (blockIdx.x < NN) {
        int n = blockIdx.x;
        if (j < 7) sx[j] = x[n * 7 + j];
        __syncthreads();
        float a = encb[j];
#pragma unroll
        for (int k = 0; k < 7; k++) a = fmaf(sx[k], encW[k * HD + j], a);
        int w = j >> 5, lane = j & 31;
        float s = warpsum(a);
        if (lane == 0) red[w] = s;
        __syncthreads();
        float m = (red[0] + red[1] + red[2] + red[3]) * (1.0f / HD);
        float d = a - m;
        float q = warpsum(d * d);
        if (lane == 0) red[4 + w] = q;
        __syncthreads();
        float var = (red[4] + red[5] + red[6] + red[7]) * (1.0f / HD);
        float t = d * rsqrtf(var + 1e-5f) * encg[j] + encbt[j];
        g_h[(size_t)n * HD + j] = gelu(t);
    } else {
        int e = blockIdx.x - NN;
        if (j < 8) sx[j] = eattr[e * 8 + j];
        __syncthreads();
        float a = eeb[j];
#pragma unroll
        for (int k = 0; k < 8; k++) a = fmaf(sx[k], eeW[k * HD + j], a);
        g_ea[(size_t)e * HD + j] = a;
    }
}

// ---------------- node projections P1 = h@W1a + b1, P2 = h@W1b ----------------
__global__ void __launch_bounds__(256, 2) k_P(int w1Off, const float* __restrict__ b1) {
    extern __shared__ float sm[];
    uint32_t* hHi = (uint32_t*)sm;          // 64 x 68
    uint32_t* hLo = hHi + 64 * 68;
    uint32_t* sWh = hHi + 2 * 64 * 68;      // 16 x 260
    uint32_t* sWl = sWh + 16 * 260;
    int tid = threadIdx.x, lane = tid & 31, wid = tid >> 5;
    int g = lane >> 2, tig = lane & 3;
    int base = blockIdx.x * 64;
    int part = blockIdx.y;
    const uint32_t* hiP = g_Wb + w1Off;
    const uint32_t* loP = hiP + 49152;   // 192*256
    float* out = part ? g_P2 : g_P1;

    for (int t = tid; t < 64 * 32; t += 256) {
        int i = t >> 5, q = t & 31;
        int n = base + i;
        float4 v = (n < NN) ? ((const float4*)g_h)[(size_t)n * 32 + q]
                            : make_float4(0, 0, 0, 0);
        uint32_t h0, l0, h1, l1;
        split2(v.x, v.y, h0, l0);
        split2(v.z, v.w, h1, l1);
        hHi[i * 68 + 2 * q] = h0; hHi[i * 68 + 2 * q + 1] = h1;
        hLo[i * 68 + 2 * q] = l0; hLo[i * 68 + 2 * q + 1] = l1;
    }

    int rowg = (wid >> 2) * 32;
    int cb1 = (wid & 3) * 64;
    float4 acc[2][8];
#pragma unroll
    for (int mt = 0; mt < 2; mt++)
#pragma unroll
        for (int nt = 0; nt < 8; nt++) acc[mt][nt] = make_float4(0, 0, 0, 0);
    for (int kc = 0; kc < 4; kc++) {
        __syncthreads();
        stage16(sWh, sWl, hiP, loP, part * 64 + kc * 16, 256, 260, tid);
        __syncthreads();
        mma_chunk_bf<8>(hHi, hLo, 68, rowg, kc * 16, sWh, sWl, 260, cb1, acc, lane);
    }
#pragma unroll
    for (int mt = 0; mt < 2; mt++) {
        int r0 = base + rowg + mt * 16 + g;
#pragma unroll
        for (int nt = 0; nt < 8; nt++) {
            int C = cb1 + nt * 8 + 2 * tig;
            float bx = part ? 0.f : __ldg(&b1[C]);
            float by = part ? 0.f : __ldg(&b1[C + 1]);
            if (r0 < NN)
                *(float2*)&out[(size_t)r0 * 256 + C] =
                    make_float2(acc[mt][nt].x + bx, acc[mt][nt].y + by);
            if (r0 + 8 < NN)
                *(float2*)&out[(size_t)(r0 + 8) * 256 + C] =
                    make_float2(acc[mt][nt].z + bx, acc[mt][nt].w + by);
        }
    }
}

// single-pass LN reduction macro body (sum + sumsq, one barrier)
#define LN_REDUCE(NTC, ACC, INVN)                                              \
    float p[2][2] = {{0, 0}, {0, 0}}, q[2][2] = {{0, 0}, {0, 0}};              \
    _Pragma("unroll")                                                          \
    for (int mt = 0; mt < 2; mt++)                                             \
        _Pragma("unroll")                                                      \
        for (int nt = 0; nt < NTC; nt++) {                                     \
            p[mt][0] += ACC[mt][nt].x + ACC[mt][nt].y;                         \
            q[mt][0] += ACC[mt][nt].x * ACC[mt][nt].x + ACC[mt][nt].y * ACC[mt][nt].y; \
            p[mt][1] += ACC[mt][nt].z + ACC[mt][nt].w;                         \
            q[mt][1] += ACC[mt][nt].z * ACC[mt][nt].z + ACC[mt][nt].w * ACC[mt][nt].w; \
        }                                                                      \
    _Pragma("unroll")                                                          \
    for (int mt = 0; mt < 2; mt++)                                             \
        _Pragma("unroll")                                                      \
        for (int h = 0; h < 2; h++) {                                          \
            p[mt][h] += __shfl_xor_sync(0xffffffffu, p[mt][h], 1);             \
            p[mt][h] += __shfl_xor_sync(0xffffffffu, p[mt][h], 2);             \
            q[mt][h] += __shfl_xor_sync(0xffffffffu, q[mt][h], 1);             \
            q[mt][h] += __shfl_xor_sync(0xffffffffu, q[mt][h], 2);             \
        }                                                                      \
    if (tig == 0)                                                              \
        _Pragma("unroll")                                                      \
        for (int mt = 0; mt < 2; mt++)                                         \
            _Pragma("unroll")                                                  \
            for (int h = 0; h < 2; h++) {                                      \
                int ri = (rowg + mt * 16 + h * 8 + g) * 4 + wcol;              \
                sRed[ri] = p[mt][h];                                           \
                sRed[256 + ri] = q[mt][h];                                     \
            }                                                                  \
    __syncthreads();                                                           \
    float m[2][2], rn[2][2];                                                   \
    _Pragma("unroll")                                                          \
    for (int mt = 0; mt < 2; mt++)                                             \
        _Pragma("unroll")                                                      \
        for (int h = 0; h < 2; h++) {                                          \
            int ri = (rowg + mt * 16 + h * 8 + g) * 4;                         \
            float4 s = *(const float4*)&sRed[ri];                              \
            float4 s2 = *(const float4*)&sRed[256 + ri];                       \
            float mm = (s.x + s.y + s.z + s.w) * (INVN);                       \
            float qq = (s2.x + s2.y + s2.z + s2.w) * (INVN);                   \
            m[mt][h] = mm;                                                     \
            rn[mt][h] = rsqrtf(qq - mm * mm + 1e-5f);                          \
        }

// ---------------- fused edge update ----------------
__global__ void __launch_bounds__(256, 2) k_edge(
    int w1Off, int w2Off,
    const float* __restrict__ g1, const float* __restrict__ bt1,
    const float* __restrict__ b2, const float* __restrict__ g2,
    const float* __restrict__ bt2) {
    extern __shared__ float sm[];
    uint32_t* buf = (uint32_t*)sm;
    uint32_t* eHi = buf;                 // 64 x 68 (GEMM1 A)
    uint32_t* eLo = buf + 64 * 68;
    uint32_t* tHi = buf;                 // 64 x 132 (GEMM2 A, aliased)
    uint32_t* tLo = buf + 64 * 132;
    uint32_t* sWh = buf + 16896;         // G1: 16x260 (+lo at +4160); G2: 32x132 (+lo at +4224)
    __shared__ int sRow[64], sCol[64];
    __shared__ __align__(16) float sRed[512];
    __shared__ float sP[896];
    int tid = threadIdx.x, lane = tid & 31, wid = tid >> 5;
    int g = lane >> 2, tig = lane & 3;
    int base = blockIdx.x * 64;
    const uint32_t* hi1 = g_Wb + w1Off;
    const uint32_t* lo1 = hi1 + 49152;
    const uint32_t* hi2 = g_Wb + w2Off;
    const uint32_t* lo2 = hi2 + 16384;

    if (tid < 64) { sRow[tid] = g_row[base + tid]; sCol[tid] = g_col[base + tid]; }
    for (int t = tid; t < 896; t += 256)
        sP[t] = (t < 256) ? g1[t] : (t < 512) ? bt1[t - 256]
              : (t < 640) ? b2[t - 512] : (t < 768) ? g2[t - 640] : bt2[t - 768];

    for (int t = tid; t < 64 * 32; t += 256) {   // ea tile -> packed bf16 planes
        int e = t >> 5, q = t & 31;
        float4 v = ((const float4*)g_ea)[(size_t)(base + e) * 32 + q];
        uint32_t h0, l0, h1, l1;
        split2(v.x, v.y, h0, l0);
        split2(v.z, v.w, h1, l1);
        eHi[e * 68 + 2 * q] = h0; eHi[e * 68 + 2 * q + 1] = h1;
        eLo[e * 68 + 2 * q] = l0; eLo[e * 68 + 2 * q + 1] = l1;
    }
    __syncthreads();   // sRow/sCol visible for gather

    int rowg = (wid >> 2) * 32;
    int cb1 = (wid & 3) * 64;
    int wcol = wid & 3;

    // GEMM1 acc init: per-fragment gather of P1[row] + P2[col]
    float4 acc[2][8];
#pragma unroll
    for (int mt = 0; mt < 2; mt++) {
        int r0 = rowg + mt * 16 + g, r1 = r0 + 8;
        const float* p1a = &g_P1[(size_t)sRow[r0] * 256];
        const float* p2a = &g_P2[(size_t)sCol[r0] * 256];
        const float* p1b = &g_P1[(size_t)sRow[r1] * 256];
        const float* p2b = &g_P2[(size_t)sCol[r1] * 256];
#pragma unroll
        for (int nt = 0; nt < 8; nt++) {
            int C = cb1 + nt * 8 + 2 * tig;
            float2 u1 = *(const float2*)&p1a[C];
            float2 u2 = *(const float2*)&p2a[C];
            float2 v1 = *(const float2*)&p1b[C];
            float2 v2 = *(const float2*)&p2b[C];
            acc[mt][nt] = make_float4(u1.x + u2.x, u1.y + u2.y,
                                      v1.x + v2.x, v1.y + v2.y);
        }
    }
    for (int kc = 0; kc < 4; kc++) {
        __syncthreads();
        stage16(sWh, sWh + 4160, hi1, lo1, 128 + kc * 16, 256, 260, tid);
        __syncthreads();
        mma_chunk_bf<8>(eHi, eLo, 68, rowg, kc * 16, sWh, sWh + 4160, 260, cb1, acc, lane);
    }

    // LN(256) + GELU -> t (packed, aliased over eHi/eLo)
    {
        LN_REDUCE(8, acc, 1.0f / 256)
#pragma unroll
        for (int mt = 0; mt < 2; mt++) {
            int r0 = rowg + mt * 16 + g;
#pragma unroll
            for (int nt = 0; nt < 8; nt++) {
                int C = cb1 + nt * 8 + 2 * tig;
                int cp = C >> 1;
                float gx = sP[C], gy = sP[C + 1];
                float bx = sP[256 + C], by = sP[256 + C + 1];
                float tx = gelu((acc[mt][nt].x - m[mt][0]) * rn[mt][0] * gx + bx);
                float ty = gelu((acc[mt][nt].y - m[mt][0]) * rn[mt][0] * gy + by);
                float tz = gelu((acc[mt][nt].z - m[mt][1]) * rn[mt][1] * gx + bx);
                float tw = gelu((acc[mt][nt].w - m[mt][1]) * rn[mt][1] * gy + by);
                uint32_t h0, l0, h1, l1;
                split2(tx, ty, h0, l0);
                split2(tz, tw, h1, l1);
                tHi[r0 * 132 + cp] = h0; tLo[r0 * 132 + cp] = l0;
                tHi[(r0 + 8) * 132 + cp] = h1; tLo[(r0 + 8) * 132 + cp] = l1;
            }
        }
    }

    // GEMM2: t @ W2  (M=64, N=128, K=256), 4 phases of K=64
    int cb2 = (wid & 3) * 32;
    float4 acc2[2][4];
#pragma unroll
    for (int mt = 0; mt < 2; mt++)
#pragma unroll
        for (int nt = 0; nt < 4; nt++) acc2[mt][nt] = make_float4(0, 0, 0, 0);
    for (int kc = 0; kc < 4; kc++) {
        __syncthreads();
        stage32n128(sWh, sWh + 4224, hi2, lo2, kc * 32, tid);
        __syncthreads();
        mma_chunk_bf<4>(tHi, tLo, 132, rowg, kc * 32, sWh, sWh + 4224, 132, cb2, acc2, lane);
        mma_chunk_bf<4>(tHi, tLo, 132, rowg, kc * 32 + 16,
                        sWh + 16 * 132, sWh + 4224 + 16 * 132, 132, cb2, acc2, lane);
    }

    // + b2, LN(128), residual (re-read g_ea), store + scatter
    {
#pragma unroll
        for (int mt = 0; mt < 2; mt++)
#pragma unroll
            for (int nt = 0; nt < 4; nt++) {
                int C = cb2 + nt * 8 + 2 * tig;
                acc2[mt][nt].x += sP[512 + C]; acc2[mt][nt].y += sP[512 + C + 1];
                acc2[mt][nt].z += sP[512 + C]; acc2[mt][nt].w += sP[512 + C + 1];
            }
        LN_REDUCE(4, acc2, 1.0f / 128)
#pragma unroll
        for (int mt = 0; mt < 2; mt++) {
            int r0 = rowg + mt * 16 + g;
            int r1 = r0 + 8;
#pragma unroll
            for (int nt = 0; nt < 4; nt++) {
                int C = cb2 + nt * 8 + 2 * tig;
                float gx = sP[640 + C], gy = sP[640 + C + 1];
                float bx = sP[768 + C], by = sP[768 + C + 1];
                float2 e0 = *(const float2*)&g_ea[(size_t)(base + r0) * HD + C];
                float2 e1 = *(const float2*)&g_ea[(size_t)(base + r1) * HD + C];
                float ox = e0.x + (acc2[mt][nt].x - m[mt][0]) * rn[mt][0] * gx + bx;
                float oy = e0.y + (acc2[mt][nt].y - m[mt][0]) * rn[mt][0] * gy + by;
                float oz = e1.x + (acc2[mt][nt].z - m[mt][1]) * rn[mt][1] * gx + bx;
                float ow = e1.y + (acc2[mt][nt].w - m[mt][1]) * rn[mt][1] * gy + by;
                *(float2*)&g_ea[(size_t)(base + r0) * HD + C] = make_float2(ox, oy);
                *(float2*)&g_ea[(size_t)(base + r1) * HD + C] = make_float2(oz, ow);
                float* a0 = &g_agg[(size_t)sCol[r0] * HD + C];
                float* a1 = &g_agg[(size_t)sCol[r1] * HD + C];
                asm volatile("red.global.add.v2.f32 [%0], {%1,%2};"
                             :: "l"(a0), "f"(ox), "f"(oy) : "memory");
                asm volatile("red.global.add.v2.f32 [%0], {%1,%2};"
                             :: "l"(a1), "f"(oz), "f"(ow) : "memory");
            }
        }
    }
}

// ---------------- fused node update ----------------
__global__ void __launch_bounds__(256, 2) k_node(
    int w1Off, int w2Off,
    const float* __restrict__ b1, const float* __restrict__ g1,
    const float* __restrict__ bt1, const float* __restrict__ b2,
    const float* __restrict__ g2, const float* __restrict__ bt2) {
    extern __shared__ float sm[];
    uint32_t* aHi = (uint32_t*)sm;            // 64 x 132 packed (K=256)
    uint32_t* aLo = aHi + 64 * 132;
    uint32_t* sWh = aHi + 16896;              // G1: 16x260; G2: 32x132
    uint32_t* tHi = aHi;                      // alias after GEMM1
    uint32_t* tLo = aLo;
    __shared__ __align__(16) float sRed[512];
    __shared__ float sP[1152];
    int tid = threadIdx.x, lane = tid & 31, wid = tid >> 5;
    int g = lane >> 2, tig = lane & 3;
    int base = blockIdx.x * 64;
    const uint32_t* hi1 = g_Wb + w1Off;
    const uint32_t* lo1 = hi1 + 32768;
    const uint32_t* hi2 = g_Wb + w2Off;
    const uint32_t* lo2 = hi2 + 16384;

    for (int t = tid; t < 1152; t += 256)
        sP[t] = (t < 256) ? b1[t] : (t < 512) ? g1[t - 256] : (t < 768) ? bt1[t - 512]
              : (t < 896) ? b2[t - 768] : (t < 1024) ? g2[t - 896] : bt2[t - 1024];

    for (int t = tid; t < 64 * 32; t += 256) {   // h -> packed cols 0..63
        int i = t >> 5, q = t & 31;
        int n = base + i;
        float4 v = (n < NN) ? ((const float4*)g_h)[(size_t)n * 32 + q]
                            : make_float4(0, 0, 0, 0);
        uint32_t h0, l0, h1, l1;
        split2(v.x, v.y, h0, l0);
        split2(v.z, v.w, h1, l1);
        aHi[i * 132 + 2 * q] = h0; aHi[i * 132 + 2 * q + 1] = h1;
        aLo[i * 132 + 2 * q] = l0; aLo[i * 132 + 2 * q + 1] = l1;
    }
    for (int t = tid; t < 64 * 32; t += 256) {   // agg*inv -> packed cols 64..127
        int i = t >> 5, q = t & 31;
        int n = base + i;
        float4 v = make_float4(0, 0, 0, 0);
        if (n < NN) {
            float4* ap = (float4*)&g_agg[(size_t)n * HD + q * 4];
            v = *ap;
            float iv = g_inv[n];
            v.x *= iv; v.y *= iv; v.z *= iv; v.w *= iv;
            *ap = make_float4(0, 0, 0, 0);
        }
        uint32_t h0, l0, h1, l1;
        split2(v.x, v.y, h0, l0);
        split2(v.z, v.w, h1, l1);
        aHi[i * 132 + 64 + 2 * q] = h0; aHi[i * 132 + 64 + 2 * q + 1] = h1;
        aLo[i * 132 + 64 + 2 * q] = l0; aLo[i * 132 + 64 + 2 * q + 1] = l1;
    }
    __syncthreads();

    int rowg = (wid >> 2) * 32;
    int cb1 = (wid & 3) * 64;
    int wcol = wid & 3;

    // GEMM1 (M=64, N=256, K=256), acc init = b1
    float4 acc[2][8];
#pragma unroll
    for (int mt = 0; mt < 2; mt++)
#pragma unroll
        for (int nt = 0; nt < 8; nt++) {
            int C = cb1 + nt * 8 + 2 * tig;
            acc[mt][nt] = make_float4(sP[C], sP[C + 1], sP[C], sP[C + 1]);
        }
    for (int kc = 0; kc < 8; kc++) {
        __syncthreads();
        stage16(sWh, sWh + 4160, hi1, lo1, kc * 16, 256, 260, tid);
        __syncthreads();
        mma_chunk_bf<8>(aHi, aLo, 132, rowg, kc * 16, sWh, sWh + 4160, 260, cb1, acc, lane);
    }

    // LN(256) + GELU -> t packed (aliased on A)
    {
        LN_REDUCE(8, acc, 1.0f / 256)
#pragma unroll
        for (int mt = 0; mt < 2; mt++) {
            int r0 = rowg + mt * 16 + g;
#pragma unroll
            for (int nt = 0; nt < 8; nt++) {
                int C = cb1 + nt * 8 + 2 * tig;
                int cp = C >> 1;
                float gx = sP[256 + C], gy = sP[256 + C + 1];
                float bx = sP[512 + C], by = sP[512 + C + 1];
                float tx = gelu((acc[mt][nt].x - m[mt][0]) * rn[mt][0] * gx + bx);
                float ty = gelu((acc[mt][nt].y - m[mt][0]) * rn[mt][0] * gy + by);
                float tz = gelu((acc[mt][nt].z - m[mt][1]) * rn[mt][1] * gx + bx);
                float tw = gelu((acc[mt][nt].w - m[mt][1]) * rn[mt][1] * gy + by);
                uint32_t h0, l0, h1, l1;
                split2(tx, ty, h0, l0);
                split2(tz, tw, h1, l1);
                tHi[r0 * 132 + cp] = h0; tLo[r0 * 132 + cp] = l0;
                tHi[(r0 + 8) * 132 + cp] = h1; tLo[(r0 + 8) * 132 + cp] = l1;
            }
        }
    }

    // GEMM2 (M=64, N=128, K=256), 4 phases of K=64
    int cb2 = (wid & 3) * 32;
    float4 acc2[2][4];
#pragma unroll
    for (int mt = 0; mt < 2; mt++)
#pragma unroll
        for (int nt = 0; nt < 4; nt++) acc2[mt][nt] = make_float4(0, 0, 0, 0);
    for (int kc = 0; kc < 4; kc++) {
        __syncthreads();
        stage32n128(sWh, sWh + 4224, hi2, lo2, kc * 32, tid);
        __syncthreads();
        mma_chunk_bf<4>(tHi, tLo, 132, rowg, kc * 32, sWh, sWh + 4224, 132, cb2, acc2, lane);
        mma_chunk_bf<4>(tHi, tLo, 132, rowg, kc * 32 + 16,
                        sWh + 16 * 132, sWh + 4224 + 16 * 132, 132, cb2, acc2, lane);
    }

    // + b2, LN(128), residual from g_h, store h
    {
#pragma unroll
        for (int mt = 0; mt < 2; mt++)
#pragma unroll
            for (int nt = 0; nt < 4; nt++) {
                int C = cb2 + nt * 8 + 2 * tig;
                acc2[mt][nt].x += sP[768 + C]; acc2[mt][nt].y += sP[768 + C + 1];
                acc2[mt][nt].z += sP[768 + C]; acc2[mt][nt].w += sP[768 + C + 1];
            }
        LN_REDUCE(4, acc2, 1.0f / 128)
#pragma unroll
        for (int mt = 0; mt < 2; mt++) {
            int r0 = rowg + mt * 16 + g;
            int r1 = r0 + 8;
            int n0 = base + r0, n1 = base + r1;
#pragma unroll
            for (int nt = 0; nt < 4; nt++) {
                int C = cb2 + nt * 8 + 2 * tig;
                float gx = sP[896 + C], gy = sP[896 + C + 1];
                float bx = sP[1024 + C], by = sP[1024 + C + 1];
                if (n0 < NN) {
                    float2 hr = *(const float2*)&g_h[(size_t)n0 * HD + C];
                    float ox = hr.x + (acc2[mt][nt].x - m[mt][0]) * rn[mt][0] * gx + bx;
                    float oy = hr.y + (acc2[mt][nt].y - m[mt][0]) * rn[mt][0] * gy + by;
                    *(float2*)&g_h[(size_t)n0 * HD + C] = make_float2(ox, oy);
                }
                if (n1 < NN) {
                    float2 hr = *(const float2*)&g_h[(size_t)n1 * HD + C];
                    float oz = hr.x + (acc2[mt][nt].z - m[mt][1]) * rn[mt][1] * gx + bx;
                    float ow = hr.y + (acc2[mt][nt].w - m[mt][1]) * rn[mt][1] * gy + by;
                    *(float2*)&g_h[(size_t)n1 * HD + C] = make_float2(oz, ow);
                }
            }
        }
    }
}

// ---------------- decoder ----------------
__global__ void k_dec(const float* __restrict__ W1, const float* __restrict__ b1,
                      const float* __restrict__ W2, const float* __restrict__ b2,
                      float* __restrict__ out) {
    int n = blockIdx.x, j = threadIdx.x;
    __shared__ float sh[128];
    __shared__ float st[128];
    sh[j] = g_h[(size_t)n * HD + j];
    __syncthreads();
    float a = b1[j];
#pragma unroll 8
    for (int k = 0; k < 128; k++) a = fmaf(sh[k], W1[k * HD + j], a);
    st[j] = gelu(a);
    __syncthreads();
    int w = j >> 5, lane = j & 31;
    float s = 0;
#pragma unroll
    for (int k = lane; k < 128; k += 32) s = fmaf(st[k], W2[k * 4 + w], s);
    s = warpsum(s);
    if (lane == 0) out[(size_t)n * 4 + w] = s + b2[w];
}

// ---------------- launch ----------------
extern "C" void kernel_launch(void* const* d_in, const int* in_sizes, int n_in,
                              void* d_out, int out_size) {
    (void)in_sizes; (void)n_in; (void)out_size;
    const float* x       = (const float*)d_in[0];
    const void*  ei      = d_in[1];
    const float* eattr   = (const float*)d_in[2];
    const float* enc_W   = (const float*)d_in[3];
    const float* enc_b   = (const float*)d_in[4];
    const float* enc_g   = (const float*)d_in[5];
    const float* enc_bt  = (const float*)d_in[6];
    const float* ee_W    = (const float*)d_in[7];
    const float* ee_b    = (const float*)d_in[8];
    const float* eW1     = (const float*)d_in[9];
    const float* eb1     = (const float*)d_in[10];
    const float* eg1     = (const float*)d_in[11];
    const float* ebt1    = (const float*)d_in[12];
    const float* eW2     = (const float*)d_in[13];
    const float* eb2     = (const float*)d_in[14];
    const float* eg2     = (const float*)d_in[15];
    const float* ebt2    = (const float*)d_in[16];
    const float* nW1     = (const float*)d_in[17];
    const float* nb1     = (const float*)d_in[18];
    const float* ng1     = (const float*)d_in[19];
    const float* nbt1    = (const float*)d_in[20];
    const float* nW2     = (const float*)d_in[21];
    const float* nb2     = (const float*)d_in[22];
    const float* ng2     = (const float*)d_in[23];
    const float* nbt2    = (const float*)d_in[24];
    const float* dec_W1  = (const float*)d_in[25];
    const float* dec_b1  = (const float*)d_in[26];
    const float* dec_W2  = (const float*)d_in[27];
    const float* dec_b2  = (const float*)d_in[28];

    cudaFuncSetAttribute(k_edge, cudaFuncAttributeMaxDynamicSharedMemorySize, EDGE_SMEM);
    cudaFuncSetAttribute(k_node, cudaFuncAttributeMaxDynamicSharedMemorySize, NODE_SMEM);
    cudaFuncSetAttribute(k_P,    cudaFuncAttributeMaxDynamicSharedMemorySize, P_SMEM);

    uint32_t* wb = nullptr;
    cudaGetSymbolAddress((void**)&wb, g_Wb);

    // Launch order arranged so ncu (-s 5 -c 1) captures k_edge (launch idx 5).
    k_detect<<<1, 32>>>(ei);                                         // 0
    k_convert<<<(NE + 255) / 256, 256>>>(ei);                        // 1
    k_encee<<<NN + NE, 128>>>(x, enc_W, enc_b, enc_g, enc_bt,
                              eattr, ee_W, ee_b);                    // 2
    k_prepAll<<<dim3(448, 10), 256>>>(eW1, eW2, nW1, nW2, wb);       // 3

    const int nodeBlocks = (NN + 63) / 64;  // 782
    k_P<<<dim3(nodeBlocks, 2), 256, P_SMEM>>>(EW1_OFF, eb1);         // 4
    k_edge<<<NE / 64, 256, EDGE_SMEM>>>(EW1_OFF, EW2_OFF,
        eg1, ebt1, eb2, eg2, ebt2);                                  // 5  <- profiled
    k_inv<<<(NN + 255) / 256, 256>>>();                              // 6
    k_node<<<nodeBlocks, 256, NODE_SMEM>>>(NW1_OFF, NW2_OFF,
        nb1, ng1, nbt1, nb2, ng2, nbt2);                             // 7

    for (int l = 1; l < 10; l++) {
        k_P<<<dim3(nodeBlocks, 2), 256, P_SMEM>>>(EW1_OFF + l * 98304, eb1 + l * 256);
        k_edge<<<NE / 64, 256, EDGE_SMEM>>>(
            EW1_OFF + l * 98304, EW2_OFF + l * 32768,
            eg1 + l * 256, ebt1 + l * 256,
            eb2 + l * 128, eg2 + l * 128, ebt2 + l * 128);
        k_node<<<nodeBlocks, 256, NODE_SMEM>>>(
            NW1_OFF + l * 65536, NW2_OFF + l * 32768,
            nb1 + l * 256, ng1 + l * 256, nbt1 + l * 256,
            nb2 + l * 128, ng2 + l * 128, nbt2 + l * 128);
    }
    k_dec<<<NN, 128>>>(dec_W1, dec_b1, dec_W2, dec_b2, (float*)d_out);
}

// round 9
// speedup vs baseline: 1.1254x; 1.0358x over previous
#include <cuda_runtime.h>
#include <cuda_bf16.h>
#include <cstdint>

#define NN 50000
#define NE 600000
#define HD 128

#define EDGE_SMEM 101376   // 25344 u32 * 4 (A-union 16896 + G1dbuf overlap + G2dbuf)
#define NODE_SMEM 101376
#define P_SMEM    68096

// packed-weight plane offsets in g_Wb (uint32 units)
#define EW1_OFF 0          // per layer 2*192*256 = 98304
#define EW2_OFF 983040     // per layer 2*128*128 = 32768
#define NW1_OFF 1310720    // per layer 2*128*256 = 65536
#define NW2_OFF 1966080    // per layer 32768
#define WB_TOTAL 2293760

// ---------------- device scratch ----------------
__device__ float g_h[NN * HD];
__device__ float g_ea[(size_t)NE * HD];
__device__ float g_P1[(size_t)NN * 256];
__device__ float g_P2[(size_t)NN * 256];
__device__ float g_agg[NN * HD];
__device__ float g_inv[NN];
__device__ int   g_cnt[NN];
__device__ int   g_row[NE];
__device__ int   g_col[NE];
__device__ uint32_t g_Wb[WB_TOTAL];

// ---------------- helpers ----------------
__device__ __forceinline__ float gelu(float x) { return x * normcdff(x); }

__device__ __forceinline__ uint32_t pack2(float a, float b) {
    uint32_t r;
    asm("cvt.rn.bf16x2.f32 %0, %1, %2;" : "=r"(r) : "f"(b), "f"(a));
    return r;
}

__device__ __forceinline__ void split2(float a, float b, uint32_t& hi, uint32_t& lo) {
    hi = pack2(a, b);
    float ra = a - __uint_as_float(hi << 16);
    float rb = b - __uint_as_float(hi & 0xffff0000u);
    lo = pack2(ra, rb);
}

__device__ __forceinline__ void mma_bf(float4& d, const uint32_t* a,
                                       uint32_t b0, uint32_t b1) {
    asm("mma.sync.aligned.m16n8k16.row.col.f32.bf16.bf16.f32 "
        "{%0,%1,%2,%3},{%4,%5,%6,%7},{%8,%9},{%0,%1,%2,%3};"
        : "+f"(d.x), "+f"(d.y), "+f"(d.z), "+f"(d.w)
        : "r"(a[0]), "r"(a[1]), "r"(a[2]), "r"(a[3]), "r"(b0), "r"(b1));
}

__device__ __forceinline__ void cpa16(void* sdst, const void* gsrc) {
    uint32_t sa = (uint32_t)__cvta_generic_to_shared(sdst);
    asm volatile("cp.async.cg.shared.global [%0], [%1], 16;" :: "r"(sa), "l"(gsrc));
}
__device__ __forceinline__ void cp_commit() {
    asm volatile("cp.async.commit_group;" ::: "memory");
}
__device__ __forceinline__ void cp_wait1() {
    asm volatile("cp.async.wait_group 1;" ::: "memory");
}
__device__ __forceinline__ void cp_wait0() {
    asm volatile("cp.async.wait_group 0;" ::: "memory");
}

// async-stage one G1 weight chunk: 16 rows x 256 u32, hi at s, lo at s+4160, ld 260
__device__ __forceinline__ void issueG1(uint32_t* s,
                                        const uint32_t* __restrict__ hiP,
                                        const uint32_t* __restrict__ loP,
                                        int kpBase, int tid) {
    for (int t = tid; t < 16 * 64; t += 256) {
        int r = t >> 6, q = t & 63;
        cpa16(&s[r * 260 + q * 4], &hiP[(size_t)(kpBase + r) * 256 + q * 4]);
        cpa16(&s[4160 + r * 260 + q * 4], &loP[(size_t)(kpBase + r) * 256 + q * 4]);
    }
    cp_commit();
}

// async-stage one G2 weight chunk: 16 rows x 128 u32, hi at s, lo at s+2112, ld 132
__device__ __forceinline__ void issueG2(uint32_t* s,
                                        const uint32_t* __restrict__ hiP,
                                        const uint32_t* __restrict__ loP,
                                        int kpBase, int tid) {
    for (int t = tid; t < 16 * 32; t += 256) {
        int r = t >> 5, q = t & 31;
        cpa16(&s[r * 132 + q * 4], &hiP[(size_t)(kpBase + r) * 128 + q * 4]);
        cpa16(&s[2112 + r * 132 + q * 4], &loP[(size_t)(kpBase + r) * 128 + q * 4]);
    }
    cp_commit();
}

// synchronous staging (k_P / k_node)
__device__ __forceinline__ void stage16(uint32_t* sWh, uint32_t* sWl,
                                        const uint32_t* __restrict__ hiP,
                                        const uint32_t* __restrict__ loP,
                                        int kpBase, int N, int ld, int tid) {
    int q4n = N >> 2;
    for (int t = tid; t < 16 * q4n; t += 256) {
        int r = t / q4n, q = t - r * q4n;
        *(uint4*)&sWh[r * ld + q * 4] = *(const uint4*)&hiP[(size_t)(kpBase + r) * N + q * 4];
        *(uint4*)&sWl[r * ld + q * 4] = *(const uint4*)&loP[(size_t)(kpBase + r) * N + q * 4];
    }
}

__device__ __forceinline__ void stage32n128(uint32_t* sWh, uint32_t* sWl,
                                            const uint32_t* __restrict__ hiP,
                                            const uint32_t* __restrict__ loP,
                                            int kpBase, int tid) {
    for (int t = tid; t < 32 * 32; t += 256) {
        int r = t >> 5, q = t & 31;
        *(uint4*)&sWh[r * 132 + q * 4] = *(const uint4*)&hiP[(size_t)(kpBase + r) * 128 + q * 4];
        *(uint4*)&sWl[r * 132 + q * 4] = *(const uint4*)&loP[(size_t)(kpBase + r) * 128 + q * 4];
    }
}

// One k32 chunk (two m16n8k16 steps), 3-term bf16-split MMA.
template <int NT>
__device__ __forceinline__ void mma_chunk_bf(
    const uint32_t* sAh, const uint32_t* sAl, int ldA, int aRow, int kpOff,
    const uint32_t* sWh, const uint32_t* sWl, int ldW, int cb,
    float4 (&acc)[2][NT], int lane) {
    int g = lane >> 2, tig = lane & 3;
#pragma unroll
    for (int ks = 0; ks < 2; ks++) {
        int cbase = kpOff + ks * 8;
        uint32_t ah[2][4], al[2][4];
#pragma unroll
        for (int mt = 0; mt < 2; mt++) {
            int r0 = aRow + mt * 16 + g, r1 = r0 + 8;
            ah[mt][0] = sAh[r0 * ldA + cbase + tig];
            ah[mt][1] = sAh[r1 * ldA + cbase + tig];
            ah[mt][2] = sAh[r0 * ldA + cbase + tig + 4];
            ah[mt][3] = sAh[r1 * ldA + cbase + tig + 4];
            al[mt][0] = sAl[r0 * ldA + cbase + tig];
            al[mt][1] = sAl[r1 * ldA + cbase + tig];
            al[mt][2] = sAl[r0 * ldA + cbase + tig + 4];
            al[mt][3] = sAl[r1 * ldA + cbase + tig + 4];
        }
        int wr0 = ks * 8 + tig, wr1 = wr0 + 4;
#pragma unroll
        for (int nt = 0; nt < NT; nt++) {
            int n = cb + nt * 8 + g;
            uint32_t bh0 = sWh[wr0 * ldW + n], bh1 = sWh[wr1 * ldW + n];
            uint32_t bl0 = sWl[wr0 * ldW + n], bl1 = sWl[wr1 * ldW + n];
#pragma unroll
            for (int mt = 0; mt < 2; mt++) {
                mma_bf(acc[mt][nt], ah[mt], bh0, bh1);
                mma_bf(acc[mt][nt], ah[mt], bl0, bl1);
                mma_bf(acc[mt][nt], al[mt], bh0, bh1);
            }
        }
    }
}

// ---------------- fused weight pre-split (all 4 groups, one launch) ----------------
__global__ void k_prepAll(const float* __restrict__ eW1, const float* __restrict__ eW2,
                          const float* __restrict__ nW1, const float* __restrict__ nW2,
                          uint32_t* __restrict__ wb) {
    int l = blockIdx.y;
    int idx = blockIdx.x * 256 + threadIdx.x;   // < 114688
    const float* W;
    uint32_t* hp;
    int KP, N, rel;
    if (idx < 49152)      { rel = idx;          W = eW1 + (size_t)l * 98304; hp = wb + EW1_OFF + l * 98304; KP = 192; N = 256; }
    else if (idx < 65536) { rel = idx - 49152;  W = eW2 + (size_t)l * 32768; hp = wb + EW2_OFF + l * 32768; KP = 128; N = 128; }
    else if (idx < 98304) { rel = idx - 65536;  W = nW1 + (size_t)l * 65536; hp = wb + NW1_OFF + l * 65536; KP = 128; N = 256; }
    else                  { rel = idx - 98304;  W = nW2 + (size_t)l * 32768; hp = wb + NW2_OFF + l * 32768; KP = 128; N = 128; }
    int kp = rel / N, n = rel - kp * N;
    float w0 = W[(size_t)(2 * kp) * N + n];
    float w1 = W[(size_t)(2 * kp + 1) * N + n];
    uint32_t hi, lo;
    split2(w0, w1, hi, lo);
    hp[(size_t)kp * N + n] = hi;
    hp[(size_t)KP * N + (size_t)kp * N + n] = lo;
}

// ---------------- fused encoders + edge-index convert/deg ----------------
__device__ __forceinline__ float warpsum(float s) {
#pragma unroll
    for (int o = 16; o; o >>= 1) s += __shfl_xor_sync(0xffffffffu, s, o);
    return s;
}

#define CONV_BLOCKS ((NE + 127) / 128)

__global__ void k_encconv(const float* __restrict__ x, const float* __restrict__ encW,
                          const float* __restrict__ encb, const float* __restrict__ encg,
                          const float* __restrict__ encbt,
                          const float* __restrict__ eattr, const float* __restrict__ eeW,
                          const float* __restrict__ eeb,
                          const void* __restrict__ ei) {
    __shared__ float sx[8];
    __shared__ float red[8];
    __shared__ int sOk;
    int j = threadIdx.x;
    if (blockIdx.x < NN) {
        int n = blockIdx.x;
        if (j < 7) sx[j] = x[n * 7 + j];
        __syncthreads();
        float a = encb[j];
#pragma unroll
        for (int k = 0; k < 7; k++) a = fmaf(sx[k], encW[k * HD + j], a);
        int w = j >> 5, lane = j & 31;
        float s = warpsum(a);
        if (lane == 0) red[w] = s;
        __syncthreads();
        float m = (red[0] + red[1] + red[2] + red[3]) * (1.0f / HD);
        float d = a - m;
        float q = warpsum(d * d);
        if (lane == 0) red[4 + w] = q;
        __syncthreads();
        float var = (red[4] + red[5] + red[6] + red[7]) * (1.0f / HD);
        float t = d * rsqrtf(var + 1e-5f) * encg[j] + encbt[j];
        g_h[(size_t)n * HD + j] = gelu(t);
    } else if (blockIdx.x < NN + NE) {
        int e = blockIdx.x - NN;
        if (j < 8) sx[j] = eattr[e * 8 + j];
        __syncthreads();
        float a = eeb[j];
#pragma unroll
        for (int k = 0; k < 8; k++) a = fmaf(sx[k], eeW[k * HD + j], a);
        g_ea[(size_t)e * HD + j] = a;
    } else {
        // edge-index convert + degree count; local int64-vs-int32 detection
        if (j == 0) sOk = 1;
        __syncthreads();
        if (j < 64) {
            long long v = ((const long long*)ei)[j];
            if (v < 0 || v >= NN) sOk = 0;
        }
        __syncthreads();
        int is64 = sOk;
        int e = (blockIdx.x - NN - NE) * 128 + j;
        if (e < NE) {
            int r, c;
            if (is64) {
                const long long* p = (const long long*)ei;
                r = (int)p[e]; c = (int)p[NE + e];
            } else {
                const int* p = (const int*)ei;
                r = p[e]; c = p[NE + e];
            }
            g_row[e] = r;
            g_col[e] = c;
            atomicAdd(&g_cnt[c], 1);
        }
    }
}

__global__ void k_inv() {
    int n = blockIdx.x * blockDim.x + threadIdx.x;
    if (n < NN) {
        g_inv[n] = 1.0f / fmaxf((float)g_cnt[n], 1.0f);
        g_cnt[n] = 0;
    }
}

// ---------------- node projections P1 = h@W1a + b1, P2 = h@W1b ----------------
__global__ void __launch_bounds__(256, 2) k_P(int w1Off, const float* __restrict__ b1) {
    extern __shared__ float sm[];
    uint32_t* hHi = (uint32_t*)sm;          // 64 x 68
    uint32_t* hLo = hHi + 64 * 68;
    uint32_t* sWh = hHi + 2 * 64 * 68;      // 16 x 260
    uint32_t* sWl = sWh + 16 * 260;
    int tid = threadIdx.x, lane = tid & 31, wid = tid >> 5;
    int g = lane >> 2, tig = lane & 3;
    int base = blockIdx.x * 64;
    int part = blockIdx.y;
    const uint32_t* hiP = g_Wb + w1Off;
    const uint32_t* loP = hiP + 49152;
    float* out = part ? g_P2 : g_P1;

    for (int t = tid; t < 64 * 32; t += 256) {
        int i = t >> 5, q = t & 31;
        int n = base + i;
        float4 v = (n < NN) ? ((const float4*)g_h)[(size_t)n * 32 + q]
                            : make_float4(0, 0, 0, 0);
        uint32_t h0, l0, h1, l1;
        split2(v.x, v.y, h0, l0);
        split2(v.z, v.w, h1, l1);
        hHi[i * 68 + 2 * q] = h0; hHi[i * 68 + 2 * q + 1] = h1;
        hLo[i * 68 + 2 * q] = l0; hLo[i * 68 + 2 * q + 1] = l1;
    }

    int rowg = (wid >> 2) * 32;
    int cb1 = (wid & 3) * 64;
    float4 acc[2][8];
#pragma unroll
    for (int mt = 0; mt < 2; mt++)
#pragma unroll
        for (int nt = 0; nt < 8; nt++) acc[mt][nt] = make_float4(0, 0, 0, 0);
    for (int kc = 0; kc < 4; kc++) {
        __syncthreads();
        stage16(sWh, sWl, hiP, loP, part * 64 + kc * 16, 256, 260, tid);
        __syncthreads();
        mma_chunk_bf<8>(hHi, hLo, 68, rowg, kc * 16, sWh, sWl, 260, cb1, acc, lane);
    }
#pragma unroll
    for (int mt = 0; mt < 2; mt++) {
        int r0 = base + rowg + mt * 16 + g;
#pragma unroll
        for (int nt = 0; nt < 8; nt++) {
            int C = cb1 + nt * 8 + 2 * tig;
            float bx = part ? 0.f : __ldg(&b1[C]);
            float by = part ? 0.f : __ldg(&b1[C + 1]);
            if (r0 < NN)
                *(float2*)&out[(size_t)r0 * 256 + C] =
                    make_float2(acc[mt][nt].x + bx, acc[mt][nt].y + by);
            if (r0 + 8 < NN)
                *(float2*)&out[(size_t)(r0 + 8) * 256 + C] =
                    make_float2(acc[mt][nt].z + bx, acc[mt][nt].w + by);
        }
    }
}

// single-pass LN reduction (sum + sumsq, one barrier)
#define LN_REDUCE(NTC, ACC, INVN)                                              \
    float p[2][2] = {{0, 0}, {0, 0}}, q[2][2] = {{0, 0}, {0, 0}};              \
    _Pragma("unroll")                                                          \
    for (int mt = 0; mt < 2; mt++)                                             \
        _Pragma("unroll")                                                      \
        for (int nt = 0; nt < NTC; nt++) {                                     \
            p[mt][0] += ACC[mt][nt].x + ACC[mt][nt].y;                         \
            q[mt][0] += ACC[mt][nt].x * ACC[mt][nt].x + ACC[mt][nt].y * ACC[mt][nt].y; \
            p[mt][1] += ACC[mt][nt].z + ACC[mt][nt].w;                         \
            q[mt][1] += ACC[mt][nt].z * ACC[mt][nt].z + ACC[mt][nt].w * ACC[mt][nt].w; \
        }                                                                      \
    _Pragma("unroll")                                                          \
    for (int mt = 0; mt < 2; mt++)                                             \
        _Pragma("unroll")                                                      \
        for (int h = 0; h < 2; h++) {                                          \
            p[mt][h] += __shfl_xor_sync(0xffffffffu, p[mt][h], 1);             \
            p[mt][h] += __shfl_xor_sync(0xffffffffu, p[mt][h], 2);             \
            q[mt][h] += __shfl_xor_sync(0xffffffffu, q[mt][h], 1);             \
            q[mt][h] += __shfl_xor_sync(0xffffffffu, q[mt][h], 2);             \
        }                                                                      \
    if (tig == 0)                                                              \
        _Pragma("unroll")                                                      \
        for (int mt = 0; mt < 2; mt++)                                         \
            _Pragma("unroll")                                                  \
            for (int h = 0; h < 2; h++) {                                      \
                int ri = (rowg + mt * 16 + h * 8 + g) * 4 + wcol;              \
                sRed[ri] = p[mt][h];                                           \
                sRed[256 + ri] = q[mt][h];                                     \
            }                                                                  \
    __syncthreads();                                                           \
    float m[2][2], rn[2][2];                                                   \
    _Pragma("unroll")                                                          \
    for (int mt = 0; mt < 2; mt++)                                             \
        _Pragma("unroll")                                                      \
        for (int h = 0; h < 2; h++) {                                          \
            int ri = (rowg + mt * 16 + h * 8 + g) * 4;                         \
            float4 s = *(const float4*)&sRed[ri];                              \
            float4 s2 = *(const float4*)&sRed[256 + ri];                       \
            float mm = (s.x + s.y + s.z + s.w) * (INVN);                       \
            float qq = (s2.x + s2.y + s2.z + s2.w) * (INVN);                   \
            m[mt][h] = mm;                                                     \
            rn[mt][h] = rsqrtf(qq - mm * mm + 1e-5f);                          \
        }

// ---------------- fused edge update (cp.async double-buffered weights) ----------------
// smem (u32): eHi [0,4352) eLo [4352,8704)  | tHi [0,8448) tLo [8448,16896)
//             G1 wbuf [8704,25344): 2 x 8320 (hi 4160 + lo 4160)
//             G2 wbuf [16896,25344): 2 x 4224 (hi 2112 + lo 2112)
__global__ void __launch_bounds__(256, 2) k_edge(
    int w1Off, int w2Off,
    const float* __restrict__ g1, const float* __restrict__ bt1,
    const float* __restrict__ b2, const float* __restrict__ g2,
    const float* __restrict__ bt2) {
    extern __shared__ float sm[];
    uint32_t* buf = (uint32_t*)sm;
    uint32_t* eHi = buf;
    uint32_t* eLo = buf + 4352;
    uint32_t* tHi = buf;
    uint32_t* tLo = buf + 8448;
    uint32_t* w1b = buf + 8704;
    uint32_t* w2b = buf + 16896;
    __shared__ int sRow[64], sCol[64];
    __shared__ __align__(16) float sRed[512];
    __shared__ float sP[896];
    int tid = threadIdx.x, lane = tid & 31, wid = tid >> 5;
    int g = lane >> 2, tig = lane & 3;
    int base = blockIdx.x * 64;
    const uint32_t* hi1 = g_Wb + w1Off;
    const uint32_t* lo1 = hi1 + 49152;
    const uint32_t* hi2 = g_Wb + w2Off;
    const uint32_t* lo2 = hi2 + 16384;

    // prefetch GEMM1 weight chunks 0,1 (fly under A staging + gather)
    issueG1(w1b, hi1, lo1, 128, tid);
    issueG1(w1b + 8320, hi1, lo1, 144, tid);

    if (tid < 64) { sRow[tid] = g_row[base + tid]; sCol[tid] = g_col[base + tid]; }
    for (int t = tid; t < 896; t += 256)
        sP[t] = (t < 256) ? g1[t] : (t < 512) ? bt1[t - 256]
              : (t < 640) ? b2[t - 512] : (t < 768) ? g2[t - 640] : bt2[t - 768];

    for (int t = tid; t < 64 * 32; t += 256) {   // ea tile -> packed bf16 planes
        int e = t >> 5, q = t & 31;
        float4 v = ((const float4*)g_ea)[(size_t)(base + e) * 32 + q];
        uint32_t h0, l0, h1, l1;
        split2(v.x, v.y, h0, l0);
        split2(v.z, v.w, h1, l1);
        eHi[e * 68 + 2 * q] = h0; eHi[e * 68 + 2 * q + 1] = h1;
        eLo[e * 68 + 2 * q] = l0; eLo[e * 68 + 2 * q + 1] = l1;
    }
    __syncthreads();   // sRow/sCol + A visible

    int rowg = (wid >> 2) * 32;
    int cb1 = (wid & 3) * 64;
    int wcol = wid & 3;

    // GEMM1 acc init: per-fragment gather of P1[row] + P2[col] (overlaps cp.async)
    float4 acc[2][8];
#pragma unroll
    for (int mt = 0; mt < 2; mt++) {
        int r0 = rowg + mt * 16 + g, r1 = r0 + 8;
        const float* p1a = &g_P1[(size_t)sRow[r0] * 256];
        const float* p2a = &g_P2[(size_t)sCol[r0] * 256];
        const float* p1b = &g_P1[(size_t)sRow[r1] * 256];
        const float* p2b = &g_P2[(size_t)sCol[r1] * 256];
#pragma unroll
        for (int nt = 0; nt < 8; nt++) {
            int C = cb1 + nt * 8 + 2 * tig;
            float2 u1 = *(const float2*)&p1a[C];
            float2 u2 = *(const float2*)&p2a[C];
            float2 v1 = *(const float2*)&p1b[C];
            float2 v2 = *(const float2*)&p2b[C];
            acc[mt][nt] = make_float4(u1.x + u2.x, u1.y + u2.y,
                                      v1.x + v2.x, v1.y + v2.y);
        }
    }

    // GEMM1 pipelined: K=128, 4 chunks of 16 packed rows
    for (int kc = 0; kc < 4; kc++) {
        if (kc < 3) cp_wait1(); else cp_wait0();
        __syncthreads();
        uint32_t* wbuf = w1b + (kc & 1) * 8320;
        mma_chunk_bf<8>(eHi, eLo, 68, rowg, kc * 16, wbuf, wbuf + 4160, 260, cb1, acc, lane);
        __syncthreads();
        if (kc + 2 < 4)
            issueG1(w1b + (kc & 1) * 8320, hi1, lo1, 128 + (kc + 2) * 16, tid);
    }

    // prefetch GEMM2 chunks 0,1 (loads fly under the LN phase)
    issueG2(w2b, hi2, lo2, 0, tid);
    issueG2(w2b + 4224, hi2, lo2, 16, tid);

    // LN(256) + GELU -> t (packed, aliased over eHi/eLo + dead G1 buf0 head)
    {
        LN_REDUCE(8, acc, 1.0f / 256)
#pragma unroll
        for (int mt = 0; mt < 2; mt++) {
            int r0 = rowg + mt * 16 + g;
#pragma unroll
            for (int nt = 0; nt < 8; nt++) {
                int C = cb1 + nt * 8 + 2 * tig;
                int cp = C >> 1;
                float gx = sP[C], gy = sP[C + 1];
                float bx = sP[256 + C], by = sP[256 + C + 1];
                float tx = gelu((acc[mt][nt].x - m[mt][0]) * rn[mt][0] * gx + bx);
                float ty = gelu((acc[mt][nt].y - m[mt][0]) * rn[mt][0] * gy + by);
                float tz = gelu((acc[mt][nt].z - m[mt][1]) * rn[mt][1] * gx + bx);
                float tw = gelu((acc[mt][nt].w - m[mt][1]) * rn[mt][1] * gy + by);
                uint32_t h0, l0, h1, l1;
                split2(tx, ty, h0, l0);
                split2(tz, tw, h1, l1);
                tHi[r0 * 132 + cp] = h0; tLo[r0 * 132 + cp] = l0;
                tHi[(r0 + 8) * 132 + cp] = h1; tLo[(r0 + 8) * 132 + cp] = l1;
            }
        }
    }

    // GEMM2 pipelined: K=256, 8 chunks of 16 packed rows
    int cb2 = (wid & 3) * 32;
    float4 acc2[2][4];
#pragma unroll
    for (int mt = 0; mt < 2; mt++)
#pragma unroll
        for (int nt = 0; nt < 4; nt++) acc2[mt][nt] = make_float4(0, 0, 0, 0);
    for (int kc = 0; kc < 8; kc++) {
        if (kc < 7) cp_wait1(); else cp_wait0();
        __syncthreads();
        uint32_t* wbuf = w2b + (kc & 1) * 4224;
        mma_chunk_bf<4>(tHi, tLo, 132, rowg, kc * 16, wbuf, wbuf + 2112, 132, cb2, acc2, lane);
        __syncthreads();
        if (kc + 2 < 8)
            issueG2(w2b + (kc & 1) * 4224, hi2, lo2, (kc + 2) * 16, tid);
    }

    // + b2, LN(128), residual (re-read g_ea), store + scatter
    {
#pragma unroll
        for (int mt = 0; mt < 2; mt++)
#pragma unroll
            for (int nt = 0; nt < 4; nt++) {
                int C = cb2 + nt * 8 + 2 * tig;
                acc2[mt][nt].x += sP[512 + C]; acc2[mt][nt].y += sP[512 + C + 1];
                acc2[mt][nt].z += sP[512 + C]; acc2[mt][nt].w += sP[512 + C + 1];
            }
        LN_REDUCE(4, acc2, 1.0f / 128)
#pragma unroll
        for (int mt = 0; mt < 2; mt++) {
            int r0 = rowg + mt * 16 + g;
            int r1 = r0 + 8;
#pragma unroll
            for (int nt = 0; nt < 4; nt++) {
                int C = cb2 + nt * 8 + 2 * tig;
                float gx = sP[640 + C], gy = sP[640 + C + 1];
                float bx = sP[768 + C], by = sP[768 + C + 1];
                float2 e0 = *(const float2*)&g_ea[(size_t)(base + r0) * HD + C];
                float2 e1 = *(const float2*)&g_ea[(size_t)(base + r1) * HD + C];
                float ox = e0.x + (acc2[mt][nt].x - m[mt][0]) * rn[mt][0] * gx + bx;
                float oy = e0.y + (acc2[mt][nt].y - m[mt][0]) * rn[mt][0] * gy + by;
                float oz = e1.x + (acc2[mt][nt].z - m[mt][1]) * rn[mt][1] * gx + bx;
                float ow = e1.y + (acc2[mt][nt].w - m[mt][1]) * rn[mt][1] * gy + by;
                *(float2*)&g_ea[(size_t)(base + r0) * HD + C] = make_float2(ox, oy);
                *(float2*)&g_ea[(size_t)(base + r1) * HD + C] = make_float2(oz, ow);
                float* a0 = &g_agg[(size_t)sCol[r0] * HD + C];
                float* a1 = &g_agg[(size_t)sCol[r1] * HD + C];
                asm volatile("red.global.add.v2.f32 [%0], {%1,%2};"
                             :: "l"(a0), "f"(ox), "f"(oy) : "memory");
                asm volatile("red.global.add.v2.f32 [%0], {%1,%2};"
                             :: "l"(a1), "f"(oz), "f"(ow) : "memory");
            }
        }
    }
}

// ---------------- fused node update (synchronous, as R8) ----------------
__global__ void __launch_bounds__(256, 2) k_node(
    int w1Off, int w2Off,
    const float* __restrict__ b1, const float* __restrict__ g1,
    const float* __restrict__ bt1, const float* __restrict__ b2,
    const float* __restrict__ g2, const float* __restrict__ bt2) {
    extern __shared__ float sm[];
    uint32_t* aHi = (uint32_t*)sm;            // 64 x 132 packed (K=256)
    uint32_t* aLo = aHi + 64 * 132;
    uint32_t* sWh = aHi + 16896;
    uint32_t* tHi = aHi;
    uint32_t* tLo = aLo;
    __shared__ __align__(16) float sRed[512];
    __shared__ float sP[1152];
    int tid = threadIdx.x, lane = tid & 31, wid = tid >> 5;
    int g = lane >> 2, tig = lane & 3;
    int base = blockIdx.x * 64;
    const uint32_t* hi1 = g_Wb + w1Off;
    const uint32_t* lo1 = hi1 + 32768;
    const uint32_t* hi2 = g_Wb + w2Off;
    const uint32_t* lo2 = hi2 + 16384;

    for (int t = tid; t < 1152; t += 256)
        sP[t] = (t < 256) ? b1[t] : (t < 512) ? g1[t - 256] : (t < 768) ? bt1[t - 512]
              : (t < 896) ? b2[t - 768] : (t < 1024) ? g2[t - 896] : bt2[t - 1024];

    for (int t = tid; t < 64 * 32; t += 256) {
        int i = t >> 5, q = t & 31;
        int n = base + i;
        float4 v = (n < NN) ? ((const float4*)g_h)[(size_t)n * 32 + q]
                            : make_float4(0, 0, 0, 0);
        uint32_t h0, l0, h1, l1;
        split2(v.x, v.y, h0, l0);
        split2(v.z, v.w, h1, l1);
        aHi[i * 132 + 2 * q] = h0; aHi[i * 132 + 2 * q + 1] = h1;
        aLo[i * 132 + 2 * q] = l0; aLo[i * 132 + 2 * q + 1] = l1;
    }
    for (int t = tid; t < 64 * 32; t += 256) {
        int i = t >> 5, q = t & 31;
        int n = base + i;
        float4 v = make_float4(0, 0, 0, 0);
        if (n < NN) {
            float4* ap = (float4*)&g_agg[(size_t)n * HD + q * 4];
            v = *ap;
            float iv = g_inv[n];
            v.x *= iv; v.y *= iv; v.z *= iv; v.w *= iv;
            *ap = make_float4(0, 0, 0, 0);
        }
        uint32_t h0, l0, h1, l1;
        split2(v.x, v.y, h0, l0);
        split2(v.z, v.w, h1, l1);
        aHi[i * 132 + 64 + 2 * q] = h0; aHi[i * 132 + 64 + 2 * q + 1] = h1;
        aLo[i * 132 + 64 + 2 * q] = l0; aLo[i * 132 + 64 + 2 * q + 1] = l1;
    }
    __syncthreads();

    int rowg = (wid >> 2) * 32;
    int cb1 = (wid & 3) * 64;
    int wcol = wid & 3;

    float4 acc[2][8];
#pragma unroll
    for (int mt = 0; mt < 2; mt++)
#pragma unroll
        for (int nt = 0; nt < 8; nt++) {
            int C = cb1 + nt * 8 + 2 * tig;
            acc[mt][nt] = make_float4(sP[C], sP[C + 1], sP[C], sP[C + 1]);
        }
    for (int kc = 0; kc < 8; kc++) {
        __syncthreads();
        stage16(sWh, sWh + 4160, hi1, lo1, kc * 16, 256, 260, tid);
        __syncthreads();
        mma_chunk_bf<8>(aHi, aLo, 132, rowg, kc * 16, sWh, sWh + 4160, 260, cb1, acc, lane);
    }

    {
        LN_REDUCE(8, acc, 1.0f / 256)
#pragma unroll
        for (int mt = 0; mt < 2; mt++) {
            int r0 = rowg + mt * 16 + g;
#pragma unroll
            for (int nt = 0; nt < 8; nt++) {
                int C = cb1 + nt * 8 + 2 * tig;
                int cp = C >> 1;
                float gx = sP[256 + C], gy = sP[256 + C + 1];
                float bx = sP[512 + C], by = sP[512 + C + 1];
                float tx = gelu((acc[mt][nt].x - m[mt][0]) * rn[mt][0] * gx + bx);
                float ty = gelu((acc[mt][nt].y - m[mt][0]) * rn[mt][0] * gy + by);
                float tz = gelu((acc[mt][nt].z - m[mt][1]) * rn[mt][1] * gx + bx);
                float tw = gelu((acc[mt][nt].w - m[mt][1]) * rn[mt][1] * gy + by);
                uint32_t h0, l0, h1, l1;
                split2(tx, ty, h0, l0);
                split2(tz, tw, h1, l1);
                tHi[r0 * 132 + cp] = h0; tLo[r0 * 132 + cp] = l0;
                tHi[(r0 + 8) * 132 + cp] = h1; tLo[(r0 + 8) * 132 + cp] = l1;
            }
        }
    }

    int cb2 = (wid & 3) * 32;
    float4 acc2[2][4];
#pragma unroll
    for (int mt = 0; mt < 2; mt++)
#pragma unroll
        for (int nt = 0; nt < 4; nt++) acc2[mt][nt] = make_float4(0, 0, 0, 0);
    for (int kc = 0; kc < 4; kc++) {
        __syncthreads();
        stage32n128(sWh, sWh + 4224, hi2, lo2, kc * 32, tid);
        __syncthreads();
        mma_chunk_bf<4>(tHi, tLo, 132, rowg, kc * 32, sWh, sWh + 4224, 132, cb2, acc2, lane);
        mma_chunk_bf<4>(tHi, tLo, 132, rowg, kc * 32 + 16,
                        sWh + 16 * 132, sWh + 4224 + 16 * 132, 132, cb2, acc2, lane);
    }

    {
#pragma unroll
        for (int mt = 0; mt < 2; mt++)
#pragma unroll
            for (int nt = 0; nt < 4; nt++) {
                int C = cb2 + nt * 8 + 2 * tig;
                acc2[mt][nt].x += sP[768 + C]; acc2[mt][nt].y += sP[768 + C + 1];
                acc2[mt][nt].z += sP[768 + C]; acc2[mt][nt].w += sP[768 + C + 1];
            }
        LN_REDUCE(4, acc2, 1.0f / 128)
#pragma unroll
        for (int mt = 0; mt < 2; mt++) {
            int r0 = rowg + mt * 16 + g;
            int r1 = r0 + 8;
            int n0 = base + r0, n1 = base + r1;
#pragma unroll
            for (int nt = 0; nt < 4; nt++) {
                int C = cb2 + nt * 8 + 2 * tig;
                float gx = sP[896 + C], gy = sP[896 + C + 1];
                float bx = sP[1024 + C], by = sP[1024 + C + 1];
                if (n0 < NN) {
                    float2 hr = *(const float2*)&g_h[(size_t)n0 * HD + C];
                    float ox = hr.x + (acc2[mt][nt].x - m[mt][0]) * rn[mt][0] * gx + bx;
                    float oy = hr.y + (acc2[mt][nt].y - m[mt][0]) * rn[mt][0] * gy + by;
                    *(float2*)&g_h[(size_t)n0 * HD + C] = make_float2(ox, oy);
                }
                if (n1 < NN) {
                    float2 hr = *(const float2*)&g_h[(size_t)n1 * HD + C];
                    float oz = hr.x + (acc2[mt][nt].z - m[mt][1]) * rn[mt][1] * gx + bx;
                    float ow = hr.y + (acc2[mt][nt].w - m[mt][1]) * rn[mt][1] * gy + by;
                    *(float2*)&g_h[(size_t)n1 * HD + C] = make_float2(oz, ow);
                }
            }
        }
    }
}

// ---------------- decoder ----------------
__global__ void k_dec(const float* __restrict__ W1, const float* __restrict__ b1,
                      const float* __restrict__ W2, const float* __restrict__ b2,
                      float* __restrict__ out) {
    int n = blockIdx.x, j = threadIdx.x;
    __shared__ float sh[128];
    __shared__ float st[128];
    sh[j] = g_h[(size_t)n * HD + j];
    __syncthreads();
    float a = b1[j];
#pragma unroll 8
    for (int k = 0; k < 128; k++) a = fmaf(sh[k], W1[k * HD + j], a);
    st[j] = gelu(a);
    __syncthreads();
    int w = j >> 5, lane = j & 31;
    float s = 0;
#pragma unroll
    for (int k = lane; k < 128; k += 32) s = fmaf(st[k], W2[k * 4 + w], s);
    s = warpsum(s);
    if (lane == 0) out[(size_t)n * 4 + w] = s + b2[w];
}

// ---------------- launch ----------------
extern "C" void kernel_launch(void* const* d_in, const int* in_sizes, int n_in,
                              void* d_out, int out_size) {
    (void)in_sizes; (void)n_in; (void)out_size;
    const float* x       = (const float*)d_in[0];
    const void*  ei      = d_in[1];
    const float* eattr   = (const float*)d_in[2];
    const float* enc_W   = (const float*)d_in[3];
    const float* enc_b   = (const float*)d_in[4];
    const float* enc_g   = (const float*)d_in[5];
    const float* enc_bt  = (const float*)d_in[6];
    const float* ee_W    = (const float*)d_in[7];
    const float* ee_b    = (const float*)d_in[8];
    const float* eW1     = (const float*)d_in[9];
    const float* eb1     = (const float*)d_in[10];
    const float* eg1     = (const float*)d_in[11];
    const float* ebt1    = (const float*)d_in[12];
    const float* eW2     = (const float*)d_in[13];
    const float* eb2     = (const float*)d_in[14];
    const float* eg2     = (const float*)d_in[15];
    const float* ebt2    = (const float*)d_in[16];
    const float* nW1     = (const float*)d_in[17];
    const float* nb1     = (const float*)d_in[18];
    const float* ng1     = (const float*)d_in[19];
    const float* nbt1    = (const float*)d_in[20];
    const float* nW2     = (const float*)d_in[21];
    const float* nb2     = (const float*)d_in[22];
    const float* ng2     = (const float*)d_in[23];
    const float* nbt2    = (const float*)d_in[24];
    const float* dec_W1  = (const float*)d_in[25];
    const float* dec_b1  = (const float*)d_in[26];
    const float* dec_W2  = (const float*)d_in[27];
    const float* dec_b2  = (const float*)d_in[28];

    cudaFuncSetAttribute(k_edge, cudaFuncAttributeMaxDynamicSharedMemorySize, EDGE_SMEM);
    cudaFuncSetAttribute(k_node, cudaFuncAttributeMaxDynamicSharedMemorySize, NODE_SMEM);
    cudaFuncSetAttribute(k_P,    cudaFuncAttributeMaxDynamicSharedMemorySize, P_SMEM);

    uint32_t* wb = nullptr;
    cudaGetSymbolAddress((void**)&wb, g_Wb);

    const int nodeBlocks = (NN + 63) / 64;  // 782

    // Launch order: harness offset +2 ⇒ ncu (-s 5 -c 1) captures my index 3 = k_edge.
    k_prepAll<<<dim3(448, 10), 256>>>(eW1, eW2, nW1, nW2, wb);         // 0
    k_encconv<<<NN + NE + CONV_BLOCKS, 128>>>(x, enc_W, enc_b, enc_g,
        enc_bt, eattr, ee_W, ee_b, ei);                                // 1
    k_P<<<dim3(nodeBlocks, 2), 256, P_SMEM>>>(EW1_OFF, eb1);           // 2
    k_edge<<<NE / 64, 256, EDGE_SMEM>>>(EW1_OFF, EW2_OFF,
        eg1, ebt1, eb2, eg2, ebt2);                                    // 3 <- profiled
    k_inv<<<(NN + 255) / 256, 256>>>();                                // 4
    k_node<<<nodeBlocks, 256, NODE_SMEM>>>(NW1_OFF, NW2_OFF,
        nb1, ng1, nbt1, nb2, ng2, nbt2);                               // 5

    for (int l = 1; l < 10; l++) {
        k_P<<<dim3(nodeBlocks, 2), 256, P_SMEM>>>(EW1_OFF + l * 98304, eb1 + l * 256);
        k_edge<<<NE / 64, 256, EDGE_SMEM>>>(
            EW1_OFF + l * 98304, EW2_OFF + l * 32768,
            eg1 + l * 256, ebt1 + l * 256,
            eb2 + l * 128, eg2 + l * 128, ebt2 + l * 128);
        k_node<<<nodeBlocks, 256, NODE_SMEM>>>(
            NW1_OFF + l * 65536, NW2_OFF + l * 32768,
            nb1 + l * 256, ng1 + l * 256, nbt1 + l * 256,
            nb2 + l * 128, ng2 + l * 128, nbt2 + l * 128);
    }
    k_dec<<<NN, 128>>>(dec_W1, dec_b1, dec_W2, dec_b2, (float*)d_out);
}

// round 11
// speedup vs baseline: 1.1638x; 1.0342x over previous
#include <cuda_runtime.h>
#include <cuda_bf16.h>
#include <cstdint>

#define NN 50000
#define NE 600000
#define HD 128

#define EDGE_SMEM 101376   // 25344 u32
#define NODE_SMEM 101376
#define P_SMEM    101376

// packed-weight plane offsets in g_Wb (uint32 units)
#define EW1_OFF 0          // per layer 2*192*256 = 98304
#define EW2_OFF 983040     // per layer 2*128*128 = 32768
#define NW1_OFF 1310720    // per layer 2*128*256 = 65536
#define NW2_OFF 1966080    // per layer 32768
#define WB_TOTAL 2293760

// ---------------- device scratch ----------------
__device__ float g_h[NN * HD];
__device__ float g_ea[(size_t)NE * HD];
__device__ float g_P1[(size_t)NN * 256];
__device__ float g_P2[(size_t)NN * 256];
__device__ float g_agg[NN * HD];
__device__ float g_inv[NN];
__device__ int   g_cnt[NN];
__device__ int   g_row[NE];
__device__ int   g_col[NE];
__device__ uint32_t g_Wb[WB_TOTAL];

// ---------------- helpers ----------------
__device__ __forceinline__ float gelu(float x) { return x * normcdff(x); }

__device__ __forceinline__ uint32_t pack2(float a, float b) {
    uint32_t r;
    asm("cvt.rn.bf16x2.f32 %0, %1, %2;" : "=r"(r) : "f"(b), "f"(a));
    return r;
}

__device__ __forceinline__ void split2(float a, float b, uint32_t& hi, uint32_t& lo) {
    hi = pack2(a, b);
    float ra = a - __uint_as_float(hi << 16);
    float rb = b - __uint_as_float(hi & 0xffff0000u);
    lo = pack2(ra, rb);
}

__device__ __forceinline__ void mma_bf(float4& d, const uint32_t* a,
                                       uint32_t b0, uint32_t b1) {
    asm("mma.sync.aligned.m16n8k16.row.col.f32.bf16.bf16.f32 "
        "{%0,%1,%2,%3},{%4,%5,%6,%7},{%8,%9},{%0,%1,%2,%3};"
        : "+f"(d.x), "+f"(d.y), "+f"(d.z), "+f"(d.w)
        : "r"(a[0]), "r"(a[1]), "r"(a[2]), "r"(a[3]), "r"(b0), "r"(b1));
}

__device__ __forceinline__ void cpa16(void* sdst, const void* gsrc) {
    uint32_t sa = (uint32_t)__cvta_generic_to_shared(sdst);
    asm volatile("cp.async.cg.shared.global [%0], [%1], 16;" :: "r"(sa), "l"(gsrc));
}
__device__ __forceinline__ void cp_commit() {
    asm volatile("cp.async.commit_group;" ::: "memory");
}
__device__ __forceinline__ void cp_wait1() {
    asm volatile("cp.async.wait_group 1;" ::: "memory");
}
__device__ __forceinline__ void cp_wait0() {
    asm volatile("cp.async.wait_group 0;" ::: "memory");
}

// async-stage 16 rows x 256 u32 (hi at s, lo at s+4160, ld 260)
__device__ __forceinline__ void issueW16x256(uint32_t* s,
                                             const uint32_t* __restrict__ hiP,
                                             const uint32_t* __restrict__ loP,
                                             int kpBase, int tid) {
    for (int t = tid; t < 16 * 64; t += 256) {
        int r = t >> 6, q = t & 63;
        cpa16(&s[r * 260 + q * 4], &hiP[(size_t)(kpBase + r) * 256 + q * 4]);
        cpa16(&s[4160 + r * 260 + q * 4], &loP[(size_t)(kpBase + r) * 256 + q * 4]);
    }
    cp_commit();
}

// async-stage 8 rows x 256 u32 (hi at s, lo at s+2080, ld 260)
__device__ __forceinline__ void issueW8x256(uint32_t* s,
                                            const uint32_t* __restrict__ hiP,
                                            const uint32_t* __restrict__ loP,
                                            int kpBase, int tid) {
    for (int t = tid; t < 8 * 64; t += 256) {
        int r = t >> 6, q = t & 63;
        cpa16(&s[r * 260 + q * 4], &hiP[(size_t)(kpBase + r) * 256 + q * 4]);
        cpa16(&s[2080 + r * 260 + q * 4], &loP[(size_t)(kpBase + r) * 256 + q * 4]);
    }
    cp_commit();
}

// async-stage 16 rows x 128 u32 (hi at s, lo at s+2112, ld 132)
__device__ __forceinline__ void issueW16x128(uint32_t* s,
                                             const uint32_t* __restrict__ hiP,
                                             const uint32_t* __restrict__ loP,
                                             int kpBase, int tid) {
    for (int t = tid; t < 16 * 32; t += 256) {
        int r = t >> 5, q = t & 31;
        cpa16(&s[r * 132 + q * 4], &hiP[(size_t)(kpBase + r) * 128 + q * 4]);
        cpa16(&s[2112 + r * 132 + q * 4], &loP[(size_t)(kpBase + r) * 128 + q * 4]);
    }
    cp_commit();
}

// KS k16-steps of 3-term bf16-split MMA (KS=2 -> 16 kp chunk, KS=1 -> 8 kp chunk)
template <int NT, int KS>
__device__ __forceinline__ void mma_chunk_bf(
    const uint32_t* sAh, const uint32_t* sAl, int ldA, int aRow, int kpOff,
    const uint32_t* sWh, const uint32_t* sWl, int ldW, int cb,
    float4 (&acc)[2][NT], int lane) {
    int g = lane >> 2, tig = lane & 3;
#pragma unroll
    for (int ks = 0; ks < KS; ks++) {
        int cbase = kpOff + ks * 8;
        uint32_t ah[2][4], al[2][4];
#pragma unroll
        for (int mt = 0; mt < 2; mt++) {
            int r0 = aRow + mt * 16 + g, r1 = r0 + 8;
            ah[mt][0] = sAh[r0 * ldA + cbase + tig];
            ah[mt][1] = sAh[r1 * ldA + cbase + tig];
            ah[mt][2] = sAh[r0 * ldA + cbase + tig + 4];
            ah[mt][3] = sAh[r1 * ldA + cbase + tig + 4];
            al[mt][0] = sAl[r0 * ldA + cbase + tig];
            al[mt][1] = sAl[r1 * ldA + cbase + tig];
            al[mt][2] = sAl[r0 * ldA + cbase + tig + 4];
            al[mt][3] = sAl[r1 * ldA + cbase + tig + 4];
        }
        int wr0 = ks * 8 + tig, wr1 = wr0 + 4;
#pragma unroll
        for (int nt = 0; nt < NT; nt++) {
            int n = cb + nt * 8 + g;
            uint32_t bh0 = sWh[wr0 * ldW + n], bh1 = sWh[wr1 * ldW + n];
            uint32_t bl0 = sWl[wr0 * ldW + n], bl1 = sWl[wr1 * ldW + n];
#pragma unroll
            for (int mt = 0; mt < 2; mt++) {
                mma_bf(acc[mt][nt], ah[mt], bh0, bh1);
                mma_bf(acc[mt][nt], ah[mt], bl0, bl1);
                mma_bf(acc[mt][nt], al[mt], bh0, bh1);
            }
        }
    }
}

// ---------------- fused weight pre-split (all 4 groups, one launch) ----------------
__global__ void k_prepAll(const float* __restrict__ eW1, const float* __restrict__ eW2,
                          const float* __restrict__ nW1, const float* __restrict__ nW2,
                          uint32_t* __restrict__ wb) {
    int l = blockIdx.y;
    int idx = blockIdx.x * 256 + threadIdx.x;   // < 114688
    const float* W;
    uint32_t* hp;
    int KP, N, rel;
    if (idx < 49152)      { rel = idx;          W = eW1 + (size_t)l * 98304; hp = wb + EW1_OFF + l * 98304; KP = 192; N = 256; }
    else if (idx < 65536) { rel = idx - 49152;  W = eW2 + (size_t)l * 32768; hp = wb + EW2_OFF + l * 32768; KP = 128; N = 128; }
    else if (idx < 98304) { rel = idx - 65536;  W = nW1 + (size_t)l * 65536; hp = wb + NW1_OFF + l * 65536; KP = 128; N = 256; }
    else                  { rel = idx - 98304;  W = nW2 + (size_t)l * 32768; hp = wb + NW2_OFF + l * 32768; KP = 128; N = 128; }
    int kp = rel / N, n = rel - kp * N;
    float w0 = W[(size_t)(2 * kp) * N + n];
    float w1 = W[(size_t)(2 * kp + 1) * N + n];
    uint32_t hi, lo;
    split2(w0, w1, hi, lo);
    hp[(size_t)kp * N + n] = hi;
    hp[(size_t)KP * N + (size_t)kp * N + n] = lo;
}

// ---------------- fused encoders + edge-index convert/deg ----------------
__device__ __forceinline__ float warpsum(float s) {
#pragma unroll
    for (int o = 16; o; o >>= 1) s += __shfl_xor_sync(0xffffffffu, s, o);
    return s;
}

#define CONV_BLOCKS ((NE + 127) / 128)

__global__ void k_encconv(const float* __restrict__ x, const float* __restrict__ encW,
                          const float* __restrict__ encb, const float* __restrict__ encg,
                          const float* __restrict__ encbt,
                          const float* __restrict__ eattr, const float* __restrict__ eeW,
                          const float* __restrict__ eeb,
                          const void* __restrict__ ei) {
    __shared__ float sx[8];
    __shared__ float red[8];
    __shared__ int sOk;
    int j = threadIdx.x;
    if (blockIdx.x < NN) {
        int n = blockIdx.x;
        if (j < 7) sx[j] = x[n * 7 + j];
        __syncthreads();
        float a = encb[j];
#pragma unroll
        for (int k = 0; k < 7; k++) a = fmaf(sx[k], encW[k * HD + j], a);
        int w = j >> 5, lane = j & 31;
        float s = warpsum(a);
        if (lane == 0) red[w] = s;
        __syncthreads();
        float m = (red[0] + red[1] + red[2] + red[3]) * (1.0f / HD);
        float d = a - m;
        float q = warpsum(d * d);
        if (lane == 0) red[4 + w] = q;
        __syncthreads();
        float var = (red[4] + red[5] + red[6] + red[7]) * (1.0f / HD);
        float t = d * rsqrtf(var + 1e-5f) * encg[j] + encbt[j];
        g_h[(size_t)n * HD + j] = gelu(t);
    } else if (blockIdx.x < NN + NE) {
        int e = blockIdx.x - NN;
        if (j < 8) sx[j] = eattr[e * 8 + j];
        __syncthreads();
        float a = eeb[j];
#pragma unroll
        for (int k = 0; k < 8; k++) a = fmaf(sx[k], eeW[k * HD + j], a);
        g_ea[(size_t)e * HD + j] = a;
    } else {
        if (j == 0) sOk = 1;
        __syncthreads();
        if (j < 64) {
            long long v = ((const long long*)ei)[j];
            if (v < 0 || v >= NN) sOk = 0;
        }
        __syncthreads();
        int is64 = sOk;
        int e = (blockIdx.x - NN - NE) * 128 + j;
        if (e < NE) {
            int r, c;
            if (is64) {
                const long long* p = (const long long*)ei;
                r = (int)p[e]; c = (int)p[NE + e];
            } else {
                const int* p = (const int*)ei;
                r = p[e]; c = p[NE + e];
            }
            g_row[e] = r;
            g_col[e] = c;
            atomicAdd(&g_cnt[c], 1);
        }
    }
}

__global__ void k_inv() {
    int n = blockIdx.x * blockDim.x + threadIdx.x;
    if (n < NN) {
        g_inv[n] = 1.0f / fmaxf((float)g_cnt[n], 1.0f);
        g_cnt[n] = 0;
    }
}

// ---------------- node projections P1 = h@W1a + b1, P2 = h@W1b (pipelined) ----------------
// smem (u32): hHi [0,4352) hLo [4352,8704) wbuf [8704,25344): 2 x 8320
__global__ void __launch_bounds__(256, 2) k_P(int w1Off, const float* __restrict__ b1) {
    extern __shared__ float sm[];
    uint32_t* hHi = (uint32_t*)sm;
    uint32_t* hLo = hHi + 4352;
    uint32_t* wbf = hHi + 8704;
    int tid = threadIdx.x, lane = tid & 31, wid = tid >> 5;
    int g = lane >> 2, tig = lane & 3;
    int base = blockIdx.x * 64;
    int part = blockIdx.y;
    const uint32_t* hiP = g_Wb + w1Off;
    const uint32_t* loP = hiP + 49152;
    float* out = part ? g_P2 : g_P1;

    // prefetch weight chunks 0,1 (fly under h staging)
    issueW16x256(wbf, hiP, loP, part * 64, tid);
    issueW16x256(wbf + 8320, hiP, loP, part * 64 + 16, tid);

    for (int t = tid; t < 64 * 32; t += 256) {
        int i = t >> 5, q = t & 31;
        int n = base + i;
        float4 v = (n < NN) ? ((const float4*)g_h)[(size_t)n * 32 + q]
                            : make_float4(0, 0, 0, 0);
        uint32_t h0, l0, h1, l1;
        split2(v.x, v.y, h0, l0);
        split2(v.z, v.w, h1, l1);
        *(uint2*)&hHi[i * 68 + 2 * q] = make_uint2(h0, h1);
        *(uint2*)&hLo[i * 68 + 2 * q] = make_uint2(l0, l1);
    }
    __syncthreads();

    int rowg = (wid >> 2) * 32;
    int cb1 = (wid & 3) * 64;
    float4 acc[2][8];
#pragma unroll
    for (int mt = 0; mt < 2; mt++)
#pragma unroll
        for (int nt = 0; nt < 8; nt++) acc[mt][nt] = make_float4(0, 0, 0, 0);
    for (int kc = 0; kc < 4; kc++) {
        if (kc < 3) cp_wait1(); else cp_wait0();
        __syncthreads();
        uint32_t* wbuf = wbf + (kc & 1) * 8320;
        mma_chunk_bf<8, 2>(hHi, hLo, 68, rowg, kc * 16, wbuf, wbuf + 4160, 260, cb1, acc, lane);
        __syncthreads();
        if (kc + 2 < 4)
            issueW16x256(wbf + (kc & 1) * 8320, hiP, loP, part * 64 + (kc + 2) * 16, tid);
    }
#pragma unroll
    for (int mt = 0; mt < 2; mt++) {
        int r0 = base + rowg + mt * 16 + g;
#pragma unroll
        for (int nt = 0; nt < 8; nt++) {
            int C = cb1 + nt * 8 + 2 * tig;
            float bx = part ? 0.f : __ldg(&b1[C]);
            float by = part ? 0.f : __ldg(&b1[C + 1]);
            if (r0 < NN)
                *(float2*)&out[(size_t)r0 * 256 + C] =
                    make_float2(acc[mt][nt].x + bx, acc[mt][nt].y + by);
            if (r0 + 8 < NN)
                *(float2*)&out[(size_t)(r0 + 8) * 256 + C] =
                    make_float2(acc[mt][nt].z + bx, acc[mt][nt].w + by);
        }
    }
}

// single-pass LN reduction (sum + sumsq, one barrier)
#define LN_REDUCE(NTC, ACC, INVN)                                              \
    float p[2][2] = {{0, 0}, {0, 0}}, q[2][2] = {{0, 0}, {0, 0}};              \
    _Pragma("unroll")                                                          \
    for (int mt = 0; mt < 2; mt++)                                             \
        _Pragma("unroll")                                                      \
        for (int nt = 0; nt < NTC; nt++) {                                     \
            p[mt][0] += ACC[mt][nt].x + ACC[mt][nt].y;                         \
            q[mt][0] += ACC[mt][nt].x * ACC[mt][nt].x + ACC[mt][nt].y * ACC[mt][nt].y; \
            p[mt][1] += ACC[mt][nt].z + ACC[mt][nt].w;                         \
            q[mt][1] += ACC[mt][nt].z * ACC[mt][nt].z + ACC[mt][nt].w * ACC[mt][nt].w; \
        }                                                                      \
    _Pragma("unroll")                                                          \
    for (int mt = 0; mt < 2; mt++)                                             \
        _Pragma("unroll")                                                      \
        for (int h = 0; h < 2; h++) {                                          \
            p[mt][h] += __shfl_xor_sync(0xffffffffu, p[mt][h], 1);             \
            p[mt][h] += __shfl_xor_sync(0xffffffffu, p[mt][h], 2);             \
            q[mt][h] += __shfl_xor_sync(0xffffffffu, q[mt][h], 1);             \
            q[mt][h] += __shfl_xor_sync(0xffffffffu, q[mt][h], 2);             \
        }                                                                      \
    if (tig == 0)                                                              \
        _Pragma("unroll")                                                      \
        for (int mt = 0; mt < 2; mt++)                                         \
            _Pragma("unroll")                                                  \
            for (int h = 0; h < 2; h++) {                                      \
                int ri = (rowg + mt * 16 + h * 8 + g) * 4 + wcol;              \
                sRed[ri] = p[mt][h];                                           \
                sRed[256 + ri] = q[mt][h];                                     \
            }                                                                  \
    __syncthreads();                                                           \
    float m[2][2], rn[2][2];                                                   \
    _Pragma("unroll")                                                          \
    for (int mt = 0; mt < 2; mt++)                                             \
        _Pragma("unroll")                                                      \
        for (int h = 0; h < 2; h++) {                                          \
            int ri = (rowg + mt * 16 + h * 8 + g) * 4;                         \
            float4 s = *(const float4*)&sRed[ri];                              \
            float4 s2 = *(const float4*)&sRed[256 + ri];                       \
            float mm = (s.x + s.y + s.z + s.w) * (INVN);                       \
            float qq = (s2.x + s2.y + s2.z + s2.w) * (INVN);                   \
            m[mt][h] = mm;                                                     \
            rn[mt][h] = rsqrtf(qq - mm * mm + 1e-5f);                          \
        }

// ---------------- fused edge update (R9 proven, cp.async pipelined) ----------------
// smem (u32): eHi [0,4352) eLo [4352,8704) | tHi [0,8448) tLo [8448,16896)
//             G1 wbuf [8704,25344): 2 x 8320 ; G2 wbuf [16896,25344): 2 x 4224
__global__ void __launch_bounds__(256, 2) k_edge(
    int w1Off, int w2Off,
    const float* __restrict__ g1, const float* __restrict__ bt1,
    const float* __restrict__ b2, const float* __restrict__ g2,
    const float* __restrict__ bt2) {
    extern __shared__ float sm[];
    uint32_t* buf = (uint32_t*)sm;
    uint32_t* eHi = buf;
    uint32_t* eLo = buf + 4352;
    uint32_t* tHi = buf;
    uint32_t* tLo = buf + 8448;
    uint32_t* w1b = buf + 8704;
    uint32_t* w2b = buf + 16896;
    __shared__ int sRow[64], sCol[64];
    __shared__ __align__(16) float sRed[512];
    __shared__ float sP[896];
    int tid = threadIdx.x, lane = tid & 31, wid = tid >> 5;
    int g = lane >> 2, tig = lane & 3;
    int base = blockIdx.x * 64;
    const uint32_t* hi1 = g_Wb + w1Off;
    const uint32_t* lo1 = hi1 + 49152;
    const uint32_t* hi2 = g_Wb + w2Off;
    const uint32_t* lo2 = hi2 + 16384;

    issueW16x256(w1b, hi1, lo1, 128, tid);
    issueW16x256(w1b + 8320, hi1, lo1, 144, tid);

    if (tid < 64) { sRow[tid] = g_row[base + tid]; sCol[tid] = g_col[base + tid]; }
    for (int t = tid; t < 896; t += 256)
        sP[t] = (t < 256) ? g1[t] : (t < 512) ? bt1[t - 256]
              : (t < 640) ? b2[t - 512] : (t < 768) ? g2[t - 640] : bt2[t - 768];

    for (int t = tid; t < 64 * 32; t += 256) {   // ea tile -> packed bf16 planes
        int e = t >> 5, q = t & 31;
        float4 v = ((const float4*)g_ea)[(size_t)(base + e) * 32 + q];
        uint32_t h0, l0, h1, l1;
        split2(v.x, v.y, h0, l0);
        split2(v.z, v.w, h1, l1);
        *(uint2*)&eHi[e * 68 + 2 * q] = make_uint2(h0, h1);
        *(uint2*)&eLo[e * 68 + 2 * q] = make_uint2(l0, l1);
    }
    __syncthreads();

    int rowg = (wid >> 2) * 32;
    int cb1 = (wid & 3) * 64;
    int wcol = wid & 3;

    // GEMM1 acc init: per-fragment gather of P1[row] + P2[col]
    float4 acc[2][8];
#pragma unroll
    for (int mt = 0; mt < 2; mt++) {
        int r0 = rowg + mt * 16 + g, r1 = r0 + 8;
        const float* p1a = &g_P1[(size_t)sRow[r0] * 256];
        const float* p2a = &g_P2[(size_t)sCol[r0] * 256];
        const float* p1b = &g_P1[(size_t)sRow[r1] * 256];
        const float* p2b = &g_P2[(size_t)sCol[r1] * 256];
#pragma unroll
        for (int nt = 0; nt < 8; nt++) {
            int C = cb1 + nt * 8 + 2 * tig;
            float2 u1 = *(const float2*)&p1a[C];
            float2 u2 = *(const float2*)&p2a[C];
            float2 v1 = *(const float2*)&p1b[C];
            float2 v2 = *(const float2*)&p2b[C];
            acc[mt][nt] = make_float4(u1.x + u2.x, u1.y + u2.y,
                                      v1.x + v2.x, v1.y + v2.y);
        }
    }

    for (int kc = 0; kc < 4; kc++) {
        if (kc < 3) cp_wait1(); else cp_wait0();
        __syncthreads();
        uint32_t* wbuf = w1b + (kc & 1) * 8320;
        mma_chunk_bf<8, 2>(eHi, eLo, 68, rowg, kc * 16, wbuf, wbuf + 4160, 260, cb1, acc, lane);
        __syncthreads();
        if (kc + 2 < 4)
            issueW16x256(w1b + (kc & 1) * 8320, hi1, lo1, 128 + (kc + 2) * 16, tid);
    }

    issueW16x128(w2b, hi2, lo2, 0, tid);
    issueW16x128(w2b + 4224, hi2, lo2, 16, tid);

    // LN(256) + GELU -> t (packed, aliased over eHi/eLo region)
    {
        LN_REDUCE(8, acc, 1.0f / 256)
#pragma unroll
        for (int mt = 0; mt < 2; mt++) {
            int r0 = rowg + mt * 16 + g;
#pragma unroll
            for (int nt = 0; nt < 8; nt++) {
                int C = cb1 + nt * 8 + 2 * tig;
                int cp = C >> 1;
                float gx = sP[C], gy = sP[C + 1];
                float bx = sP[256 + C], by = sP[256 + C + 1];
                float tx = gelu((acc[mt][nt].x - m[mt][0]) * rn[mt][0] * gx + bx);
                float ty = gelu((acc[mt][nt].y - m[mt][0]) * rn[mt][0] * gy + by);
                float tz = gelu((acc[mt][nt].z - m[mt][1]) * rn[mt][1] * gx + bx);
                float tw = gelu((acc[mt][nt].w - m[mt][1]) * rn[mt][1] * gy + by);
                uint32_t h0, l0, h1, l1;
                split2(tx, ty, h0, l0);
                split2(tz, tw, h1, l1);
                tHi[r0 * 132 + cp] = h0; tLo[r0 * 132 + cp] = l0;
                tHi[(r0 + 8) * 132 + cp] = h1; tLo[(r0 + 8) * 132 + cp] = l1;
            }
        }
    }

    // GEMM2 pipelined: K=256, 8 chunks of 16 packed rows
    int cb2 = (wid & 3) * 32;
    float4 acc2[2][4];
#pragma unroll
    for (int mt = 0; mt < 2; mt++)
#pragma unroll
        for (int nt = 0; nt < 4; nt++) acc2[mt][nt] = make_float4(0, 0, 0, 0);
    for (int kc = 0; kc < 8; kc++) {
        if (kc < 7) cp_wait1(); else cp_wait0();
        __syncthreads();
        uint32_t* wbuf = w2b + (kc & 1) * 4224;
        mma_chunk_bf<4, 2>(tHi, tLo, 132, rowg, kc * 16, wbuf, wbuf + 2112, 132, cb2, acc2, lane);
        __syncthreads();
        if (kc + 2 < 8)
            issueW16x128(w2b + (kc & 1) * 4224, hi2, lo2, (kc + 2) * 16, tid);
    }

    // + b2, LN(128), residual (re-read g_ea), store + scatter
    {
#pragma unroll
        for (int mt = 0; mt < 2; mt++)
#pragma unroll
            for (int nt = 0; nt < 4; nt++) {
                int C = cb2 + nt * 8 + 2 * tig;
                acc2[mt][nt].x += sP[512 + C]; acc2[mt][nt].y += sP[512 + C + 1];
                acc2[mt][nt].z += sP[512 + C]; acc2[mt][nt].w += sP[512 + C + 1];
            }
        LN_REDUCE(4, acc2, 1.0f / 128)
#pragma unroll
        for (int mt = 0; mt < 2; mt++) {
            int r0 = rowg + mt * 16 + g;
            int r1 = r0 + 8;
#pragma unroll
            for (int nt = 0; nt < 4; nt++) {
                int C = cb2 + nt * 8 + 2 * tig;
                float gx = sP[640 + C], gy = sP[640 + C + 1];
                float bx = sP[768 + C], by = sP[768 + C + 1];
                float2 e0 = *(const float2*)&g_ea[(size_t)(base + r0) * HD + C];
                float2 e1 = *(const float2*)&g_ea[(size_t)(base + r1) * HD + C];
                float ox = e0.x + (acc2[mt][nt].x - m[mt][0]) * rn[mt][0] * gx + bx;
                float oy = e0.y + (acc2[mt][nt].y - m[mt][0]) * rn[mt][0] * gy + by;
                float oz = e1.x + (acc2[mt][nt].z - m[mt][1]) * rn[mt][1] * gx + bx;
                float ow = e1.y + (acc2[mt][nt].w - m[mt][1]) * rn[mt][1] * gy + by;
                *(float2*)&g_ea[(size_t)(base + r0) * HD + C] = make_float2(ox, oy);
                *(float2*)&g_ea[(size_t)(base + r1) * HD + C] = make_float2(oz, ow);
                float* a0 = &g_agg[(size_t)sCol[r0] * HD + C];
                float* a1 = &g_agg[(size_t)sCol[r1] * HD + C];
                asm volatile("red.global.add.v2.f32 [%0], {%1,%2};"
                             :: "l"(a0), "f"(ox), "f"(oy) : "memory");
                asm volatile("red.global.add.v2.f32 [%0], {%1,%2};"
                             :: "l"(a1), "f"(oz), "f"(ow) : "memory");
            }
        }
    }
}

// ---------------- fused node update (pipelined: G1 8-kp dbuf, G2 16-kp dbuf) ----------------
// smem (u32): aHi [0,8448) aLo [8448,16896)
//             G1 wbuf [16896,25216): 2 x 4160 ; G2 wbuf [16896,25344): 2 x 4224
__global__ void __launch_bounds__(256, 2) k_node(
    int w1Off, int w2Off,
    const float* __restrict__ b1, const float* __restrict__ g1,
    const float* __restrict__ bt1, const float* __restrict__ b2,
    const float* __restrict__ g2, const float* __restrict__ bt2) {
    extern __shared__ float sm[];
    uint32_t* aHi = (uint32_t*)sm;
    uint32_t* aLo = aHi + 8448;
    uint32_t* w1b = aHi + 16896;
    uint32_t* w2b = aHi + 16896;
    uint32_t* tHi = aHi;
    uint32_t* tLo = aLo;
    __shared__ __align__(16) float sRed[512];
    __shared__ float sP[1152];
    int tid = threadIdx.x, lane = tid & 31, wid = tid >> 5;
    int g = lane >> 2, tig = lane & 3;
    int base = blockIdx.x * 64;
    const uint32_t* hi1 = g_Wb + w1Off;
    const uint32_t* lo1 = hi1 + 32768;
    const uint32_t* hi2 = g_Wb + w2Off;
    const uint32_t* lo2 = hi2 + 16384;

    // prefetch G1 chunks 0,1 (8 kp rows each) under A staging
    issueW8x256(w1b, hi1, lo1, 0, tid);
    issueW8x256(w1b + 4160, hi1, lo1, 8, tid);

    for (int t = tid; t < 1152; t += 256)
        sP[t] = (t < 256) ? b1[t] : (t < 512) ? g1[t - 256] : (t < 768) ? bt1[t - 512]
              : (t < 896) ? b2[t - 768] : (t < 1024) ? g2[t - 896] : bt2[t - 1024];

    for (int t = tid; t < 64 * 32; t += 256) {
        int i = t >> 5, q = t & 31;
        int n = base + i;
        float4 v = (n < NN) ? ((const float4*)g_h)[(size_t)n * 32 + q]
                            : make_float4(0, 0, 0, 0);
        uint32_t h0, l0, h1, l1;
        split2(v.x, v.y, h0, l0);
        split2(v.z, v.w, h1, l1);
        *(uint2*)&aHi[i * 132 + 2 * q] = make_uint2(h0, h1);
        *(uint2*)&aLo[i * 132 + 2 * q] = make_uint2(l0, l1);
    }
    for (int t = tid; t < 64 * 32; t += 256) {
        int i = t >> 5, q = t & 31;
        int n = base + i;
        float4 v = make_float4(0, 0, 0, 0);
        if (n < NN) {
            float4* ap = (float4*)&g_agg[(size_t)n * HD + q * 4];
            v = *ap;
            float iv = g_inv[n];
            v.x *= iv; v.y *= iv; v.z *= iv; v.w *= iv;
            *ap = make_float4(0, 0, 0, 0);
        }
        uint32_t h0, l0, h1, l1;
        split2(v.x, v.y, h0, l0);
        split2(v.z, v.w, h1, l1);
        *(uint2*)&aHi[i * 132 + 64 + 2 * q] = make_uint2(h0, h1);
        *(uint2*)&aLo[i * 132 + 64 + 2 * q] = make_uint2(l0, l1);
    }
    __syncthreads();

    int rowg = (wid >> 2) * 32;
    int cb1 = (wid & 3) * 64;
    int wcol = wid & 3;

    // GEMM1 (M=64, N=256, K=256): 16 pipelined chunks of 8 kp
    float4 acc[2][8];
#pragma unroll
    for (int mt = 0; mt < 2; mt++)
#pragma unroll
        for (int nt = 0; nt < 8; nt++) {
            int C = cb1 + nt * 8 + 2 * tig;
            acc[mt][nt] = make_float4(sP[C], sP[C + 1], sP[C], sP[C + 1]);
        }
    for (int kc = 0; kc < 16; kc++) {
        if (kc < 15) cp_wait1(); else cp_wait0();
        __syncthreads();
        uint32_t* wbuf = w1b + (kc & 1) * 4160;
        mma_chunk_bf<8, 1>(aHi, aLo, 132, rowg, kc * 8, wbuf, wbuf + 2080, 260, cb1, acc, lane);
        __syncthreads();
        if (kc + 2 < 16)
            issueW8x256(w1b + (kc & 1) * 4160, hi1, lo1, (kc + 2) * 8, tid);
    }

    // prefetch G2 chunks 0,1 (fly under LN)
    issueW16x128(w2b, hi2, lo2, 0, tid);
    issueW16x128(w2b + 4224, hi2, lo2, 16, tid);

    // LN(256) + GELU -> t packed (aliased on A)
    {
        LN_REDUCE(8, acc, 1.0f / 256)
#pragma unroll
        for (int mt = 0; mt < 2; mt++) {
            int r0 = rowg + mt * 16 + g;
#pragma unroll
            for (int nt = 0; nt < 8; nt++) {
                int C = cb1 + nt * 8 + 2 * tig;
                int cp = C >> 1;
                float gx = sP[256 + C], gy = sP[256 + C + 1];
                float bx = sP[512 + C], by = sP[512 + C + 1];
                float tx = gelu((acc[mt][nt].x - m[mt][0]) * rn[mt][0] * gx + bx);
                float ty = gelu((acc[mt][nt].y - m[mt][0]) * rn[mt][0] * gy + by);
                float tz = gelu((acc[mt][nt].z - m[mt][1]) * rn[mt][1] * gx + bx);
                float tw = gelu((acc[mt][nt].w - m[mt][1]) * rn[mt][1] * gy + by);
                uint32_t h0, l0, h1, l1;
                split2(tx, ty, h0, l0);
                split2(tz, tw, h1, l1);
                tHi[r0 * 132 + cp] = h0; tLo[r0 * 132 + cp] = l0;
                tHi[(r0 + 8) * 132 + cp] = h1; tLo[(r0 + 8) * 132 + cp] = l1;
            }
        }
    }

    // GEMM2 (M=64, N=128, K=256): 8 pipelined chunks of 16 kp
    int cb2 = (wid & 3) * 32;
    float4 acc2[2][4];
#pragma unroll
    for (int mt = 0; mt < 2; mt++)
#pragma unroll
        for (int nt = 0; nt < 4; nt++) acc2[mt][nt] = make_float4(0, 0, 0, 0);
    for (int kc = 0; kc < 8; kc++) {
        if (kc < 7) cp_wait1(); else cp_wait0();
        __syncthreads();
        uint32_t* wbuf = w2b + (kc & 1) * 4224;
        mma_chunk_bf<4, 2>(tHi, tLo, 132, rowg, kc * 16, wbuf, wbuf + 2112, 132, cb2, acc2, lane);
        __syncthreads();
        if (kc + 2 < 8)
            issueW16x128(w2b + (kc & 1) * 4224, hi2, lo2, (kc + 2) * 16, tid);
    }

    // + b2, LN(128), residual from g_h, store h
    {
#pragma unroll
        for (int mt = 0; mt < 2; mt++)
#pragma unroll
            for (int nt = 0; nt < 4; nt++) {
                int C = cb2 + nt * 8 + 2 * tig;
                acc2[mt][nt].x += sP[768 + C]; acc2[mt][nt].y += sP[768 + C + 1];
                acc2[mt][nt].z += sP[768 + C]; acc2[mt][nt].w += sP[768 + C + 1];
            }
        LN_REDUCE(4, acc2, 1.0f / 128)
#pragma unroll
        for (int mt = 0; mt < 2; mt++) {
            int r0 = rowg + mt * 16 + g;
            int r1 = r0 + 8;
            int n0 = base + r0, n1 = base + r1;
#pragma unroll
            for (int nt = 0; nt < 4; nt++) {
                int C = cb2 + nt * 8 + 2 * tig;
                float gx = sP[896 + C], gy = sP[896 + C + 1];
                float bx = sP[1024 + C], by = sP[1024 + C + 1];
                if (n0 < NN) {
                    float2 hr = *(const float2*)&g_h[(size_t)n0 * HD + C];
                    float ox = hr.x + (acc2[mt][nt].x - m[mt][0]) * rn[mt][0] * gx + bx;
                    float oy = hr.y + (acc2[mt][nt].y - m[mt][0]) * rn[mt][0] * gy + by;
                    *(float2*)&g_h[(size_t)n0 * HD + C] = make_float2(ox, oy);
                }
                if (n1 < NN) {
                    float2 hr = *(const float2*)&g_h[(size_t)n1 * HD + C];
                    float oz = hr.x + (acc2[mt][nt].z - m[mt][1]) * rn[mt][1] * gx + bx;
                    float ow = hr.y + (acc2[mt][nt].w - m[mt][1]) * rn[mt][1] * gy + by;
                    *(float2*)&g_h[(size_t)n1 * HD + C] = make_float2(oz, ow);
                }
            }
        }
    }
}

// ---------------- decoder ----------------
__global__ void k_dec(const float* __restrict__ W1, const float* __restrict__ b1,
                      const float* __restrict__ W2, const float* __restrict__ b2,
                      float* __restrict__ out) {
    int n = blockIdx.x, j = threadIdx.x;
    __shared__ float sh[128];
    __shared__ float st[128];
    sh[j] = g_h[(size_t)n * HD + j];
    __syncthreads();
    float a = b1[j];
#pragma unroll 8
    for (int k = 0; k < 128; k++) a = fmaf(sh[k], W1[k * HD + j], a);
    st[j] = gelu(a);
    __syncthreads();
    int w = j >> 5, lane = j & 31;
    float s = 0;
#pragma unroll
    for (int k = lane; k < 128; k += 32) s = fmaf(st[k], W2[k * 4 + w], s);
    s = warpsum(s);
    if (lane == 0) out[(size_t)n * 4 + w] = s + b2[w];
}

// ---------------- launch ----------------
extern "C" void kernel_launch(void* const* d_in, const int* in_sizes, int n_in,
                              void* d_out, int out_size) {
    (void)in_sizes; (void)n_in; (void)out_size;
    const float* x       = (const float*)d_in[0];
    const void*  ei      = d_in[1];
    const float* eattr   = (const float*)d_in[2];
    const float* enc_W   = (const float*)d_in[3];
    const float* enc_b   = (const float*)d_in[4];
    const float* enc_g   = (const float*)d_in[5];
    const float* enc_bt  = (const float*)d_in[6];
    const float* ee_W    = (const float*)d_in[7];
    const float* ee_b    = (const float*)d_in[8];
    const float* eW1     = (const float*)d_in[9];
    const float* eb1     = (const float*)d_in[10];
    const float* eg1     = (const float*)d_in[11];
    const float* ebt1    = (const float*)d_in[12];
    const float* eW2     = (const float*)d_in[13];
    const float* eb2     = (const float*)d_in[14];
    const float* eg2     = (const float*)d_in[15];
    const float* ebt2    = (const float*)d_in[16];
    const float* nW1     = (const float*)d_in[17];
    const float* nb1     = (const float*)d_in[18];
    const float* ng1     = (const float*)d_in[19];
    const float* nbt1    = (const float*)d_in[20];
    const float* nW2     = (const float*)d_in[21];
    const float* nb2     = (const float*)d_in[22];
    const float* ng2     = (const float*)d_in[23];
    const float* nbt2    = (const float*)d_in[24];
    const float* dec_W1  = (const float*)d_in[25];
    const float* dec_b1  = (const float*)d_in[26];
    const float* dec_W2  = (const float*)d_in[27];
    const float* dec_b2  = (const float*)d_in[28];

    cudaFuncSetAttribute(k_edge, cudaFuncAttributeMaxDynamicSharedMemorySize, EDGE_SMEM);
    cudaFuncSetAttribute(k_node, cudaFuncAttributeMaxDynamicSharedMemorySize, NODE_SMEM);
    cudaFuncSetAttribute(k_P,    cudaFuncAttributeMaxDynamicSharedMemorySize, P_SMEM);

    uint32_t* wb = nullptr;
    cudaGetSymbolAddress((void**)&wb, g_Wb);

    const int nodeBlocks = (NN + 63) / 64;  // 782

    // k_edge kept at my launch index 3 (harness offset +2 -> ncu -s5 captures it)
    k_prepAll<<<dim3(448, 10), 256>>>(eW1, eW2, nW1, nW2, wb);         // 0
    k_encconv<<<NN + NE + CONV_BLOCKS, 128>>>(x, enc_W, enc_b, enc_g,
        enc_bt, eattr, ee_W, ee_b, ei);                                // 1
    k_P<<<dim3(nodeBlocks, 2), 256, P_SMEM>>>(EW1_OFF, eb1);           // 2
    k_edge<<<NE / 64, 256, EDGE_SMEM>>>(EW1_OFF, EW2_OFF,
        eg1, ebt1, eb2, eg2, ebt2);                                    // 3 <- profiled
    k_inv<<<(NN + 255) / 256, 256>>>();                                // 4
    k_node<<<nodeBlocks, 256, NODE_SMEM>>>(NW1_OFF, NW2_OFF,
        nb1, ng1, nbt1, nb2, ng2, nbt2);                               // 5

    for (int l = 1; l < 10; l++) {
        k_P<<<dim3(nodeBlocks, 2), 256, P_SMEM>>>(EW1_OFF + l * 98304, eb1 + l * 256);
        k_edge<<<NE / 64, 256, EDGE_SMEM>>>(
            EW1_OFF + l * 98304, EW2_OFF + l * 32768,
            eg1 + l * 256, ebt1 + l * 256,
            eb2 + l * 128, eg2 + l * 128, ebt2 + l * 128);
        k_node<<<nodeBlocks, 256, NODE_SMEM>>>(
            NW1_OFF + l * 65536, NW2_OFF + l * 32768,
            nb1 + l * 256, ng1 + l * 256, nbt1 + l * 256,
            nb2 + l * 128, ng2 + l * 128, nbt2 + l * 128);
    }
    k_dec<<<NN, 128>>>(dec_W1, dec_b1, dec_W2, dec_b2, (float*)d_out);
}